// round 12
// baseline (speedup 1.0000x reference)
#include <cuda_runtime.h>
#include <cuda_fp16.h>
#include <cstdint>
#include <cstddef>

// Problem constants
#define Bb   8
#define Ll   4160
#define Dd   1024
#define Hh   16
#define NBb  64
#define BLb  64
#define NSs  64
#define NTt  4096   // NB*BL
#define Mtot (Bb*Ll)      // 33280
#define K2c  2048         // row stride of fp16 operand buffers (only [0,1024) used)

// Scratch (device globals: allocation-free)
__device__ float g_Q [(size_t)Mtot*Dd];
__device__ float g_K [(size_t)Mtot*Dd];
__device__ float g_V [(size_t)Mtot*Dd];
__device__ float g_K2[(size_t)Mtot*Dd];
__device__ float g_V2[(size_t)Mtot*Dd];
__device__ float g_QS[(size_t)Bb*NSs*Dd];
__device__ float g_S [(size_t)Bb*NSs*Dd];
__device__ __half g_Xq[(size_t)Mtot*K2c];
__device__ __half g_Xk[(size_t)Mtot*K2c];
__device__ __half g_Xv[(size_t)Mtot*K2c];
__device__ __half g_Wc[5][(size_t)Dd*K2c];
__device__ float g_Wcomb[2][(size_t)Dd*Dd];
__device__ float g_bck[Dd];
__device__ float g_bcv[Dd];
__device__ float g_zero[Dd];   // zero-initialized, never written

// ===========================================================================
// helpers
// ===========================================================================
__device__ __forceinline__ uint32_t smem_u32(const void* p) {
    uint32_t a;
    asm("{ .reg .u64 t; cvta.to.shared.u64 t, %1; cvt.u32.u64 %0, t; }"
        : "=r"(a) : "l"(p));
    return a;
}
__device__ __forceinline__ void ldsm4(uint32_t* r, uint32_t addr) {
    asm volatile("ldmatrix.sync.aligned.m8n8.x4.shared.b16 {%0,%1,%2,%3}, [%4];"
                 : "=r"(r[0]), "=r"(r[1]), "=r"(r[2]), "=r"(r[3]) : "r"(addr));
}
__device__ __forceinline__ void mma16816h(float* d, const uint32_t* a,
                                          uint32_t b0, uint32_t b1) {
    asm volatile("mma.sync.aligned.m16n8k16.row.col.f32.f16.f16.f32 "
                 "{%0,%1,%2,%3}, {%4,%5,%6,%7}, {%8,%9}, {%0,%1,%2,%3};"
                 : "+f"(d[0]), "+f"(d[1]), "+f"(d[2]), "+f"(d[3])
                 : "r"(a[0]), "r"(a[1]), "r"(a[2]), "r"(a[3]), "r"(b0), "r"(b1));
}
__device__ __forceinline__ void cpasync16(uint32_t d, const void* g) {
    asm volatile("cp.async.cg.shared.global [%0], [%1], 16;" :: "r"(d), "l"(g));
}
__device__ __forceinline__ uint32_t packh2(__half a, __half b) {
    __half2 p = __halves2half2(a, b);
    return *(uint32_t*)&p;
}

// ===========================================================================
// Convert X fp32 [rows x 1024] -> Y fp16 hi-only (row stride K2c).
// ===========================================================================
__global__ void __launch_bounds__(256)
conv_hi(const float* __restrict__ X, __half* __restrict__ Y, int n4)
{
    int i = blockIdx.x * blockDim.x + threadIdx.x;
    if (i >= n4) return;
    float4 v = ((const float4*)X)[i];
    int e = i << 2;
    int row = e >> 10, col = e & 1023;
    uint2 hv = make_uint2(packh2(__float2half_rn(v.x), __float2half_rn(v.y)),
                          packh2(__float2half_rn(v.z), __float2half_rn(v.w)));
    *(uint2*)(Y + (size_t)row * K2c + col) = hv;
}

// ===========================================================================
// bias combine: out[i] = dot(W2 row i, b1) + b2[i].  grid = 1024 blocks.
// ===========================================================================
__global__ void __launch_bounds__(256)
bias_comb(const float* __restrict__ W2, const float* __restrict__ b1,
          const float* __restrict__ b2, float* __restrict__ out)
{
    __shared__ float red[256];
    int i = blockIdx.x;
    float s = 0.0f;
    for (int k = threadIdx.x; k < Dd; k += 256)
        s += W2[(size_t)i * Dd + k] * b1[k];
    red[threadIdx.x] = s;
    __syncthreads();
    for (int st = 128; st > 0; st >>= 1) {
        if (threadIdx.x < st) red[threadIdx.x] += red[threadIdx.x + st];
        __syncthreads();
    }
    if (threadIdx.x == 0) out[i] = red[0] + b2[i];
}

// ===========================================================================
// fp16 TN GEMM (2 CTA/SM): C[M,1024] = A'[M,:64*kchunks] @ W'[1024,...]^T
// ===========================================================================
#define GB_SMEM (2*32768)

__global__ void __launch_bounds__(256)
gemm_fp16(const __half* __restrict__ A, const __half* __restrict__ W,
          const float* __restrict__ bias, float* __restrict__ C, int kchunks)
{
    extern __shared__ char gsm[];
    const uint32_t sb = smem_u32(gsm);
    const int t = threadIdx.x;
    const int m0 = blockIdx.y * 128;
    const int n0 = blockIdx.x * 128;

    const int l = t & 31, wid = t >> 5;
    const int wm = (wid & 3) * 32;
    const int wn = (wid >> 2) * 64;
    const int lr = (l & 7) + ((l >> 3) & 1) * 8;
    const int khalf = l >> 4;

    uint32_t aoff[2], asw[2];
    #pragma unroll
    for (int i = 0; i < 2; i++) {
        int row = wm + i * 16 + lr;
        aoff[i] = row * 128;
        asw[i]  = row & 7;
    }
    uint32_t boff[4], bsw[4];
    #pragma unroll
    for (int pr = 0; pr < 4; pr++) {
        int row = wn + pr * 16 + lr;
        boff[pr] = row * 128;
        bsw[pr]  = row & 7;
    }

    float acc[2][8][4];
    #pragma unroll
    for (int i = 0; i < 2; i++)
        #pragma unroll
        for (int j = 0; j < 8; j++)
            #pragma unroll
            for (int z = 0; z < 4; z++) acc[i][j][z] = 0.0f;

    const int NCH = kchunks;

    auto load_chunk = [&](int s) {
        int p = s & 1;
        uint32_t sa  = sb + p * 32768;
        uint32_t sbb = sa + 16384;
        const __half* Ag = A + (size_t)m0 * K2c + s * 64;
        const __half* Wg = W + (size_t)n0 * K2c + s * 64;
        #pragma unroll
        for (int it = 0; it < 4; it++) {
            int e = it * 256 + t;
            int row = e >> 3, seg = e & 7;
            uint32_t sw = (uint32_t)((seg ^ (row & 7)) << 4);
            cpasync16(sa  + row * 128 + sw, Ag + (size_t)row * K2c + seg * 8);
            cpasync16(sbb + row * 128 + sw, Wg + (size_t)row * K2c + seg * 8);
        }
        asm volatile("cp.async.commit_group;");
    };

    load_chunk(0);

    for (int s = 0; s < NCH; s++) {
        if (s + 1 < NCH) {
            load_chunk(s + 1);
            asm volatile("cp.async.wait_group 1;");
        } else {
            asm volatile("cp.async.wait_group 0;");
        }
        __syncthreads();

        int p = s & 1;
        uint32_t sa  = sb + p * 32768;
        uint32_t sbb = sa + 16384;
        #pragma unroll
        for (int k2 = 0; k2 < 4; k2++) {
            uint32_t areg[2][4];
            #pragma unroll
            for (int i = 0; i < 2; i++)
                ldsm4(areg[i], sa + aoff[i] + ((((uint32_t)(k2*2 + khalf)) ^ asw[i]) << 4));
            uint32_t breg[4][4];
            #pragma unroll
            for (int pr = 0; pr < 4; pr++)
                ldsm4(breg[pr], sbb + boff[pr] + ((((uint32_t)(k2*2 + khalf)) ^ bsw[pr]) << 4));
            #pragma unroll
            for (int i = 0; i < 2; i++)
                #pragma unroll
                for (int j = 0; j < 8; j++)
                    mma16816h(acc[i][j], areg[i],
                              breg[j >> 1][j & 1], breg[j >> 1][2 + (j & 1)]);
        }
        __syncthreads();
    }

    const int r = l >> 2, q = l & 3;
    #pragma unroll
    for (int i = 0; i < 2; i++) {
        int row = m0 + wm + i * 16 + r;
        #pragma unroll
        for (int j = 0; j < 8; j++) {
            int col = n0 + wn + j * 8 + q * 2;
            float b0 = bias[col], b1 = bias[col + 1];
            *(float2*)(C + (size_t)row * 1024 + col) =
                make_float2(acc[i][j][0] + b0, acc[i][j][1] + b1);
            *(float2*)(C + (size_t)(row + 8) * 1024 + col) =
                make_float2(acc[i][j][2] + b0, acc[i][j][3] + b1);
        }
    }
}

// ===========================================================================
// SIMT SGEMM, 64x128 tiles (halved per-block latency for single-wave grids):
//   C = A @ op(W) + bias
// modeW: 0 -> W [N,K] row-major (A@W^T);  1 -> W [K,N] row-major (A@W)
// modeA: 1 = gather rows via sidx; modeC: 1 = scatter rows to b*L+NT+q
// Grid: (N/128, M/64). 256 threads, 8x4 per-thread tile.
// ===========================================================================
__global__ void __launch_bounds__(256)
sgemm_bias(const float* __restrict__ A, const float* __restrict__ W,
           const float* __restrict__ bias, float* __restrict__ C,
           int M, int N, int K,
           int modeA, const int* __restrict__ sidx, int modeC, int modeW)
{
    __shared__ float As[8][64];
    __shared__ float Bs[8][128];
    const int t    = threadIdx.x;
    const int row0 = blockIdx.y * 64;
    const int col0 = blockIdx.x * 128;

    // A fill: thread -> (row = t>>2, k-pair = (t&3)*2), float2
    const int a_r = t >> 2;
    const int a_c = (t & 3) << 1;
    int arow = row0 + a_r;
    size_t a_base;
    if (modeA == 1) {
        int bi = arow >> 6, qq = arow & 63;
        a_base = ((size_t)bi * Ll + (size_t)sidx[qq]) * (size_t)K;
    } else {
        a_base = (size_t)arow * (size_t)K;
    }
    // B fill (modeW=0): thread -> (n-row = t>>1, k-quad = (t&1)*4), float4
    const int b_r = t >> 1;
    const int b_c = (t & 1) << 2;
    const size_t w_base = (size_t)(col0 + b_r) * (size_t)K;
    // B fill (modeW=1)
    const int kk2 = t >> 5;
    const int n4  = (t & 31) << 2;

    const int tr = (t >> 5) << 3;   // 0..56
    const int tc = (t & 31) << 2;   // 0..124
    float acc[8][4];
    #pragma unroll
    for (int i = 0; i < 8; i++)
        #pragma unroll
        for (int j = 0; j < 4; j++) acc[i][j] = 0.0f;

    for (int k0 = 0; k0 < K; k0 += 8) {
        float2 av = *(const float2*)(A + a_base + k0 + a_c);
        As[a_c+0][a_r] = av.x; As[a_c+1][a_r] = av.y;
        if (modeW == 0) {
            float4 wv = *(const float4*)(W + w_base + k0 + b_c);
            Bs[b_c+0][b_r] = wv.x; Bs[b_c+1][b_r] = wv.y;
            Bs[b_c+2][b_r] = wv.z; Bs[b_c+3][b_r] = wv.w;
        } else {
            float4 wv = *(const float4*)(W + (size_t)(k0 + kk2) * N + col0 + n4);
            *(float4*)&Bs[kk2][n4] = wv;
        }
        __syncthreads();
        #pragma unroll
        for (int k = 0; k < 8; k++) {
            float ra[8], rb[4];
            *(float4*)&ra[0] = *(const float4*)&As[k][tr];
            *(float4*)&ra[4] = *(const float4*)&As[k][tr+4];
            *(float4*)&rb[0] = *(const float4*)&Bs[k][tc];
            #pragma unroll
            for (int i = 0; i < 8; i++)
                #pragma unroll
                for (int j = 0; j < 4; j++)
                    acc[i][j] = fmaf(ra[i], rb[j], acc[i][j]);
        }
        __syncthreads();
    }
    #pragma unroll
    for (int i = 0; i < 8; i++) {
        int r = row0 + tr + i;
        int orow = (modeC == 1) ? ((r >> 6) * Ll + NTt + (r & 63)) : r;
        float* cp = C + (size_t)orow * (size_t)N + col0 + tc;
        #pragma unroll
        for (int j = 0; j < 4; j++)
            cp[j] = acc[i][j] + bias[col0 + tc + j];
    }
}

// ===========================================================================
// Temporal block attention (parallel softmax: 4 threads/row)
// ===========================================================================
#define TA_SMEM ((4160 + 8704 + 8448 + 128) * 4)

__global__ void __launch_bounds__(256)
temporal_attn(const float* __restrict__ Q, const float* __restrict__ K,
              const float* __restrict__ V,
              const int* __restrict__ tidx, const int* __restrict__ sidx,
              const float* __restrict__ tpm, const float* __restrict__ spm,
              float* __restrict__ out)
{
    const int h = blockIdx.x, nb = blockIdx.y, b = blockIdx.z;
    const int t = threadIdx.x;
    extern __shared__ float smf[];
    float* sqT   = smf;
    float* skv   = smf + 4160;
    float* sp    = skv + 8704;
    float* sbias = sp + 8448;

    if (t < 128) {
        float mk = (t < 64) ? tpm[((b*NBb)+nb)*BLb + t] : spm[b*NSs + (t-64)];
        sbias[t] = (mk == 1.0f) ? 0.0f : -1e30f;
    }
    for (int e = t; e < 64*64; e += 256) {
        int r = e >> 6, k = e & 63;
        int grow = tidx[nb*64 + r];
        sqT[k*65 + r] = Q[((size_t)b*Ll + grow)*Dd + h*64 + k];
    }
    for (int e = t; e < 128*64; e += 256) {
        int r = e >> 6, k = e & 63;
        int grow = (r < 64) ? tidx[nb*64 + r] : sidx[r - 64];
        skv[k*132 + r] = K[((size_t)b*Ll + grow)*Dd + h*64 + k];
    }
    __syncthreads();
    {
        const int r0 = (t >> 4) << 2;
        const int c0 = (t & 15) << 3;
        float acc[4][8];
        #pragma unroll
        for (int i = 0; i < 4; i++)
            #pragma unroll
            for (int j = 0; j < 8; j++) acc[i][j] = 0.0f;
        for (int k = 0; k < 64; k++) {
            float ra[4], rb[8];
            #pragma unroll
            for (int i = 0; i < 4; i++) ra[i] = sqT[k*65 + r0 + i];
            *(float4*)&rb[0] = *(const float4*)&skv[k*132 + c0];
            *(float4*)&rb[4] = *(const float4*)&skv[k*132 + c0 + 4];
            #pragma unroll
            for (int i = 0; i < 4; i++)
                #pragma unroll
                for (int j = 0; j < 8; j++)
                    acc[i][j] = fmaf(ra[i], rb[j], acc[i][j]);
        }
        #pragma unroll
        for (int i = 0; i < 4; i++)
            #pragma unroll
            for (int j = 0; j < 8; j++)
                sp[(r0+i)*132 + c0 + j] = acc[i][j]*0.125f + sbias[c0 + j];
    }
    __syncthreads();
    for (int e = t; e < 128*64; e += 256) {
        int r = e >> 6, k = e & 63;
        int grow = (r < 64) ? tidx[nb*64 + r] : sidx[r - 64];
        skv[r*68 + k] = V[((size_t)b*Ll + grow)*Dd + h*64 + k];
    }
    // parallel softmax: 4 threads per row
    {
        const int row = t >> 2, lane4 = t & 3;
        float* rp = sp + row*132;
        float mx = -1e30f;
        for (int c = lane4; c < 128; c += 4) mx = fmaxf(mx, rp[c]);
        mx = fmaxf(mx, __shfl_xor_sync(0xFFFFFFFFu, mx, 1));
        mx = fmaxf(mx, __shfl_xor_sync(0xFFFFFFFFu, mx, 2));
        float s = 0.0f;
        for (int c = lane4; c < 128; c += 4) { float p = __expf(rp[c]-mx); rp[c] = p; s += p; }
        s += __shfl_xor_sync(0xFFFFFFFFu, s, 1);
        s += __shfl_xor_sync(0xFFFFFFFFu, s, 2);
        float inv = 1.0f / s;
        for (int c = lane4; c < 128; c += 4) rp[c] *= inv;
    }
    __syncthreads();
    {
        const int r0 = (t >> 4) << 2;
        const int c0 = (t & 15) << 2;
        float acc[4][4];
        #pragma unroll
        for (int i = 0; i < 4; i++)
            #pragma unroll
            for (int j = 0; j < 4; j++) acc[i][j] = 0.0f;
        for (int j = 0; j < 128; j++) {
            float ra[4], rb[4];
            #pragma unroll
            for (int i = 0; i < 4; i++) ra[i] = sp[(r0+i)*132 + j];
            *(float4*)&rb[0] = *(const float4*)&skv[j*68 + c0];
            #pragma unroll
            for (int i = 0; i < 4; i++)
                #pragma unroll
                for (int jj = 0; jj < 4; jj++)
                    acc[i][jj] = fmaf(ra[i], rb[jj], acc[i][jj]);
        }
        #pragma unroll
        for (int i = 0; i < 4; i++)
            #pragma unroll
            for (int jj = 0; jj < 4; jj++)
                out[((size_t)b*Ll + nb*64 + r0 + i)*Dd + h*64 + c0 + jj] = acc[i][jj];
    }
}

// ===========================================================================
// Static attention (flash-style, parallel softmax)
// ===========================================================================
#define SA_SMEM ((4160 + 4352 + 4352 + 4352 + 256) * 4)

__global__ void __launch_bounds__(256)
static_attn(const float* __restrict__ Qs, const float* __restrict__ K2,
            const float* __restrict__ V2,
            const int* __restrict__ tidx, const int* __restrict__ sidx,
            const float* __restrict__ tpm, const float* __restrict__ spm,
            float* __restrict__ S)
{
    const int h = blockIdx.x, b = blockIdx.y;
    const int t = threadIdx.x;
    extern __shared__ float smf[];
    float* sqT  = smf;
    float* skT  = smf + 4160;
    float* sv   = skT + 4352;
    float* sp   = sv + 4352;
    float* mrow = sp + 4352;
    float* lrow = mrow + 64;
    float* arow = lrow + 64;
    float* sb2  = arow + 64;

    for (int e = t; e < 4096; e += 256) {
        int r = e >> 6, k = e & 63;
        sqT[k*65 + r] = Qs[((size_t)b*64 + r)*Dd + h*64 + k];
    }
    if (t < 64) { mrow[t] = -1e30f; lrow[t] = 0.0f; }

    const int r0 = (t >> 4) << 2;
    const int c0 = (t & 15) << 2;
    float O[4][4];
    #pragma unroll
    for (int i = 0; i < 4; i++)
        #pragma unroll
        for (int j = 0; j < 4; j++) O[i][j] = 0.0f;

    for (int jc = 0; jc < 65; jc++) {
        int base = jc * 64;
        __syncthreads();
        for (int e = t; e < 4096; e += 256) {
            int j = e >> 6, k = e & 63;
            int jj = base + j;
            int grow = (jj < NTt) ? tidx[jj] : sidx[jj - NTt];
            size_t gb = ((size_t)b*Ll + grow)*Dd + h*64 + k;
            skT[k*68 + j] = K2[gb];
            sv[j*68 + k]  = V2[gb];
        }
        if (t < 64) {
            int jj = base + t;
            float mk = (jj < NTt) ? tpm[b*NTt + jj] : spm[b*NSs + (jj - NTt)];
            sb2[t] = (mk == 1.0f) ? 0.0f : -1e30f;
        }
        __syncthreads();

        float acc[4][4];
        #pragma unroll
        for (int i = 0; i < 4; i++)
            #pragma unroll
            for (int j = 0; j < 4; j++) acc[i][j] = 0.0f;
        for (int k = 0; k < 64; k++) {
            float ra[4], rb[4];
            #pragma unroll
            for (int i = 0; i < 4; i++) ra[i] = sqT[k*65 + r0 + i];
            *(float4*)&rb[0] = *(const float4*)&skT[k*68 + c0];
            #pragma unroll
            for (int i = 0; i < 4; i++)
                #pragma unroll
                for (int j = 0; j < 4; j++)
                    acc[i][j] = fmaf(ra[i], rb[j], acc[i][j]);
        }
        #pragma unroll
        for (int i = 0; i < 4; i++)
            #pragma unroll
            for (int j = 0; j < 4; j++)
                sp[(r0+i)*68 + c0 + j] = acc[i][j]*0.125f + sb2[c0 + j];
        __syncthreads();

        // parallel running softmax: 4 threads per row
        {
            const int row = t >> 2, lane4 = t & 3;
            float* rp = sp + row*68;
            float mold = mrow[row];
            float mx = mold;
            for (int c = lane4; c < 64; c += 4) mx = fmaxf(mx, rp[c]);
            mx = fmaxf(mx, __shfl_xor_sync(0xFFFFFFFFu, mx, 1));
            mx = fmaxf(mx, __shfl_xor_sync(0xFFFFFFFFu, mx, 2));
            float a = __expf(mold - mx);
            float ssum = 0.0f;
            for (int c = lane4; c < 64; c += 4) { float p = __expf(rp[c]-mx); rp[c] = p; ssum += p; }
            ssum += __shfl_xor_sync(0xFFFFFFFFu, ssum, 1);
            ssum += __shfl_xor_sync(0xFFFFFFFFu, ssum, 2);
            if (lane4 == 0) {
                lrow[row] = lrow[row]*a + ssum;
                mrow[row] = mx;
                arow[row] = a;
            }
        }
        __syncthreads();
        {
            float al[4];
            #pragma unroll
            for (int i = 0; i < 4; i++) al[i] = arow[r0 + i];
            float acc2[4][4];
            #pragma unroll
            for (int i = 0; i < 4; i++)
                #pragma unroll
                for (int j = 0; j < 4; j++) acc2[i][j] = 0.0f;
            for (int j = 0; j < 64; j++) {
                float ra[4], rb[4];
                #pragma unroll
                for (int i = 0; i < 4; i++) ra[i] = sp[(r0+i)*68 + j];
                *(float4*)&rb[0] = *(const float4*)&sv[j*68 + c0];
                #pragma unroll
                for (int i = 0; i < 4; i++)
                    #pragma unroll
                    for (int jj = 0; jj < 4; jj++)
                        acc2[i][jj] = fmaf(ra[i], rb[jj], acc2[i][jj]);
            }
            #pragma unroll
            for (int i = 0; i < 4; i++)
                #pragma unroll
                for (int j = 0; j < 4; j++)
                    O[i][j] = O[i][j]*al[i] + acc2[i][j];
        }
    }
    #pragma unroll
    for (int i = 0; i < 4; i++) {
        float inv = 1.0f / lrow[r0 + i];
        #pragma unroll
        for (int j = 0; j < 4; j++)
            S[((size_t)b*64 + r0 + i)*Dd + h*64 + c0 + j] = O[i][j]*inv;
    }
}

// ===========================================================================
extern "C" void kernel_launch(void* const* d_in, const int* in_sizes, int n_in,
                              void* d_out, int out_size)
{
    (void)in_sizes; (void)out_size;
    const float* query = (const float*)d_in[0];
    const float* key   = (const float*)d_in[1];
    const float* value = (const float*)d_in[2];
    const int*   tidx  = (const int*)  d_in[3];
    const int*   sidx  = (const int*)  d_in[4];
    const float* tpm   = (const float*)d_in[5];
    const float* spm   = (const float*)d_in[6];
    const float* outb  = (const float*)d_in[n_in-1];
    const float* outw  = (const float*)d_in[n_in-2];
    const float* ipb   = (const float*)d_in[n_in-3];
    const float* ipw   = (const float*)d_in[n_in-4];
    const float* bv    = (const float*)d_in[n_in-5];
    const float* Wv    = (const float*)d_in[n_in-6];
    const float* bk    = (const float*)d_in[n_in-7];
    const float* Wk    = (const float*)d_in[n_in-8];
    const float* bq    = (const float*)d_in[n_in-9];
    const float* Wq    = (const float*)d_in[n_in-10];
    float* out = (float*)d_out;

    float *Q, *K, *V, *K2p, *V2p, *QS, *S, *Wcomb, *bck, *bcv, *zero;
    __half *Xq, *Xk, *Xv, *Wc;
    cudaGetSymbolAddress((void**)&Q,  g_Q);
    cudaGetSymbolAddress((void**)&K,  g_K);
    cudaGetSymbolAddress((void**)&V,  g_V);
    cudaGetSymbolAddress((void**)&K2p, g_K2);
    cudaGetSymbolAddress((void**)&V2p, g_V2);
    cudaGetSymbolAddress((void**)&QS, g_QS);
    cudaGetSymbolAddress((void**)&S,  g_S);
    cudaGetSymbolAddress((void**)&Xq, g_Xq);
    cudaGetSymbolAddress((void**)&Xk, g_Xk);
    cudaGetSymbolAddress((void**)&Xv, g_Xv);
    cudaGetSymbolAddress((void**)&Wc, g_Wc);
    cudaGetSymbolAddress((void**)&Wcomb, g_Wcomb);
    cudaGetSymbolAddress((void**)&bck, g_bck);
    cudaGetSymbolAddress((void**)&bcv, g_bcv);
    cudaGetSymbolAddress((void**)&zero, g_zero);

    cudaFuncSetAttribute(gemm_fp16,     cudaFuncAttributeMaxDynamicSharedMemorySize, GB_SMEM);
    cudaFuncSetAttribute(temporal_attn, cudaFuncAttributeMaxDynamicSharedMemorySize, TA_SMEM);
    cudaFuncSetAttribute(static_attn,   cudaFuncAttributeMaxDynamicSharedMemorySize, SA_SMEM);

    static cudaStream_t s2 = 0;
    static cudaEvent_t ev0 = 0, evQx = 0, evKx = 0, evVx = 0, evQKV = 0, evQS = 0, evS2 = 0;
    if (!s2) {
        cudaStreamCreateWithFlags(&s2, cudaStreamNonBlocking);
        cudaEventCreateWithFlags(&ev0,   cudaEventDisableTiming);
        cudaEventCreateWithFlags(&evQx,  cudaEventDisableTiming);
        cudaEventCreateWithFlags(&evKx,  cudaEventDisableTiming);
        cudaEventCreateWithFlags(&evVx,  cudaEventDisableTiming);
        cudaEventCreateWithFlags(&evQKV, cudaEventDisableTiming);
        cudaEventCreateWithFlags(&evQS,  cudaEventDisableTiming);
        cudaEventCreateWithFlags(&evS2,  cudaEventDisableTiming);
    }

    dim3 blk(256);
    dim3 ggemm(Dd/128, Mtot/128);          // (8, 260)
    dim3 gsq(Dd/128, Dd/64);               // (8, 16)  weight combines (64-row tiles)
    dim3 gsm(Dd/128, (Bb*NSs)/64);         // (8, 8)   QS / out-proj
    const int wn4 = Dd*Dd/4;
    const int xn4 = Mtot*Dd/4;
    const int wblocks = (wn4 + 255)/256;
    const int xblocks = (xn4 + 255)/256;
    __half* Wc0 = Wc;
    __half* Wc1 = Wc + (size_t)1*Dd*K2c;
    __half* Wc2 = Wc + (size_t)2*Dd*K2c;
    __half* Wc3 = Wc + (size_t)3*Dd*K2c;
    __half* Wc4 = Wc + (size_t)4*Dd*K2c;
    float* Wcombk = Wcomb;
    float* Wcombv = Wcomb + (size_t)Dd*Dd;
    const float* Wk2 = ipw + (size_t)Dd*Dd;
    const float* Wv2 = ipw + (size_t)2*Dd*Dd;

    // ---- fork: s2 does the input/weight fp16 conversions (hi-only) ----
    cudaEventRecord(ev0, 0);
    cudaStreamWaitEvent(s2, ev0, 0);
    conv_hi<<<wblocks, blk, 0, s2>>>(Wq, Wc0, wn4);
    conv_hi<<<xblocks, blk, 0, s2>>>(query, Xq, xn4);
    cudaEventRecord(evQx, s2);
    conv_hi<<<wblocks, blk, 0, s2>>>(Wk, Wc1, wn4);
    conv_hi<<<xblocks, blk, 0, s2>>>(key, Xk, xn4);
    cudaEventRecord(evKx, s2);
    conv_hi<<<wblocks, blk, 0, s2>>>(Wv, Wc2, wn4);
    conv_hi<<<xblocks, blk, 0, s2>>>(value, Xv, xn4);
    cudaEventRecord(evVx, s2);

    // ---- main: weight combine (overlaps s2 convs) ----
    sgemm_bias<<<gsq, blk>>>(Wk2, Wk, zero, Wcombk, Dd, Dd, Dd, 0, sidx, 0, 1);
    sgemm_bias<<<gsq, blk>>>(Wv2, Wv, zero, Wcombv, Dd, Dd, Dd, 0, sidx, 0, 1);
    bias_comb<<<Dd, blk>>>(Wk2, bk, ipb + Dd,   bck);
    bias_comb<<<Dd, blk>>>(Wv2, bv, ipb + 2*Dd, bcv);
    conv_hi<<<wblocks, blk>>>(Wcombk, Wc3, wn4);
    conv_hi<<<wblocks, blk>>>(Wcombv, Wc4, wn4);

    // ---- main: Q/K/V GEMMs (single-term fp16, K=1024) ----
    cudaStreamWaitEvent(0, evQx, 0);
    gemm_fp16<<<ggemm, blk, GB_SMEM>>>(Xq, Wc0, bq, Q, 16);
    cudaStreamWaitEvent(0, evKx, 0);
    gemm_fp16<<<ggemm, blk, GB_SMEM>>>(Xk, Wc1, bk, K, 16);
    cudaStreamWaitEvent(0, evVx, 0);
    gemm_fp16<<<ggemm, blk, GB_SMEM>>>(Xv, Wc2, bv, V, 16);
    cudaEventRecord(evQKV, 0);

    // ---- fork: s2 = QS proj -> (evQS) -> temporal attention
    //      main = K2/V2 GEMMs -> static attention (waits only evQS) ----
    cudaStreamWaitEvent(s2, evQKV, 0);
    sgemm_bias<<<gsm, blk, 0, s2>>>(Q, ipw, ipb, QS, Bb*NSs, Dd, Dd, 1, sidx, 0, 0);
    cudaEventRecord(evQS, s2);
    temporal_attn<<<dim3(Hh, NBb, Bb), blk, TA_SMEM, s2>>>(Q, K, V, tidx, sidx, tpm, spm, out);
    cudaEventRecord(evS2, s2);

    gemm_fp16<<<ggemm, blk, GB_SMEM>>>(Xk, Wc3, bck, K2p, 16);
    gemm_fp16<<<ggemm, blk, GB_SMEM>>>(Xv, Wc4, bcv, V2p, 16);

    cudaStreamWaitEvent(0, evQS, 0);
    static_attn<<<dim3(Hh, Bb), blk, SA_SMEM>>>(QS, K2p, V2p, tidx, sidx, tpm, spm, S);
    sgemm_bias<<<gsm, blk>>>(S, outw, outb, out, Bb*NSs, Dd, Dd, 0, sidx, 1, 0);

    // join temporal branch back into main stream (capture requires rejoin)
    cudaStreamWaitEvent(0, evS2, 0);
}

// round 13
// speedup vs baseline: 1.1314x; 1.1314x over previous
#include <cuda_runtime.h>
#include <cuda_fp16.h>
#include <cstdint>
#include <cstddef>

// Problem constants
#define Bb   8
#define Ll   4160
#define Dd   1024
#define Hh   16
#define NBb  64
#define BLb  64
#define NSs  64
#define NTt  4096   // NB*BL
#define Mtot (Bb*Ll)      // 33280
#define K2c  2048         // row stride of fp16 operand buffers (only [0,1024) used)

// Scratch (device globals: allocation-free)
__device__ float g_Q [(size_t)Mtot*Dd];
__device__ float g_K [(size_t)Mtot*Dd];
__device__ float g_V [(size_t)Mtot*Dd];
__device__ float g_K2[(size_t)Mtot*Dd];
__device__ float g_V2[(size_t)Mtot*Dd];
__device__ float g_QS[(size_t)Bb*NSs*Dd];
__device__ float g_S [(size_t)Bb*NSs*Dd];
__device__ __half g_Xq[(size_t)Mtot*K2c];
__device__ __half g_Xk[(size_t)Mtot*K2c];
__device__ __half g_Xv[(size_t)Mtot*K2c];
__device__ __half g_Wc[5][(size_t)Dd*K2c];
__device__ float g_Wcomb[2][(size_t)Dd*Dd];
__device__ float g_bck[Dd];
__device__ float g_bcv[Dd];
__device__ float g_zero[Dd];   // zero-initialized, never written

// ===========================================================================
// helpers
// ===========================================================================
__device__ __forceinline__ uint32_t smem_u32(const void* p) {
    uint32_t a;
    asm("{ .reg .u64 t; cvta.to.shared.u64 t, %1; cvt.u32.u64 %0, t; }"
        : "=r"(a) : "l"(p));
    return a;
}
__device__ __forceinline__ void ldsm4(uint32_t* r, uint32_t addr) {
    asm volatile("ldmatrix.sync.aligned.m8n8.x4.shared.b16 {%0,%1,%2,%3}, [%4];"
                 : "=r"(r[0]), "=r"(r[1]), "=r"(r[2]), "=r"(r[3]) : "r"(addr));
}
__device__ __forceinline__ void mma16816h(float* d, const uint32_t* a,
                                          uint32_t b0, uint32_t b1) {
    asm volatile("mma.sync.aligned.m16n8k16.row.col.f32.f16.f16.f32 "
                 "{%0,%1,%2,%3}, {%4,%5,%6,%7}, {%8,%9}, {%0,%1,%2,%3};"
                 : "+f"(d[0]), "+f"(d[1]), "+f"(d[2]), "+f"(d[3])
                 : "r"(a[0]), "r"(a[1]), "r"(a[2]), "r"(a[3]), "r"(b0), "r"(b1));
}
__device__ __forceinline__ void cpasync16(uint32_t d, const void* g) {
    asm volatile("cp.async.cg.shared.global [%0], [%1], 16;" :: "r"(d), "l"(g));
}
__device__ __forceinline__ uint32_t packh2(__half a, __half b) {
    __half2 p = __halves2half2(a, b);
    return *(uint32_t*)&p;
}

// ===========================================================================
// Convert X fp32 [rows x 1024] -> Y fp16 hi-only (row stride K2c).
// ===========================================================================
__global__ void __launch_bounds__(256)
conv_hi(const float* __restrict__ X, __half* __restrict__ Y, int n4)
{
    int i = blockIdx.x * blockDim.x + threadIdx.x;
    if (i >= n4) return;
    float4 v = ((const float4*)X)[i];
    int e = i << 2;
    int row = e >> 10, col = e & 1023;
    uint2 hv = make_uint2(packh2(__float2half_rn(v.x), __float2half_rn(v.y)),
                          packh2(__float2half_rn(v.z), __float2half_rn(v.w)));
    *(uint2*)(Y + (size_t)row * K2c + col) = hv;
}

// ===========================================================================
// bias combine: out[i] = dot(W2 row i, b1) + b2[i].  grid = 1024 blocks.
// ===========================================================================
__global__ void __launch_bounds__(256)
bias_comb(const float* __restrict__ W2, const float* __restrict__ b1,
          const float* __restrict__ b2, float* __restrict__ out)
{
    __shared__ float red[256];
    int i = blockIdx.x;
    float s = 0.0f;
    for (int k = threadIdx.x; k < Dd; k += 256)
        s += W2[(size_t)i * Dd + k] * b1[k];
    red[threadIdx.x] = s;
    __syncthreads();
    for (int st = 128; st > 0; st >>= 1) {
        if (threadIdx.x < st) red[threadIdx.x] += red[threadIdx.x + st];
        __syncthreads();
    }
    if (threadIdx.x == 0) out[i] = red[0] + b2[i];
}

// ===========================================================================
// fp16 TN GEMM (2 CTA/SM): C[M,1024] = A'[M,:64*kchunks] @ W'[1024,...]^T
// ===========================================================================
#define GB_SMEM (2*32768)

__global__ void __launch_bounds__(256)
gemm_fp16(const __half* __restrict__ A, const __half* __restrict__ W,
          const float* __restrict__ bias, float* __restrict__ C, int kchunks)
{
    extern __shared__ char gsm[];
    const uint32_t sb = smem_u32(gsm);
    const int t = threadIdx.x;
    const int m0 = blockIdx.y * 128;
    const int n0 = blockIdx.x * 128;

    const int l = t & 31, wid = t >> 5;
    const int wm = (wid & 3) * 32;
    const int wn = (wid >> 2) * 64;
    const int lr = (l & 7) + ((l >> 3) & 1) * 8;
    const int khalf = l >> 4;

    uint32_t aoff[2], asw[2];
    #pragma unroll
    for (int i = 0; i < 2; i++) {
        int row = wm + i * 16 + lr;
        aoff[i] = row * 128;
        asw[i]  = row & 7;
    }
    uint32_t boff[4], bsw[4];
    #pragma unroll
    for (int pr = 0; pr < 4; pr++) {
        int row = wn + pr * 16 + lr;
        boff[pr] = row * 128;
        bsw[pr]  = row & 7;
    }

    float acc[2][8][4];
    #pragma unroll
    for (int i = 0; i < 2; i++)
        #pragma unroll
        for (int j = 0; j < 8; j++)
            #pragma unroll
            for (int z = 0; z < 4; z++) acc[i][j][z] = 0.0f;

    const int NCH = kchunks;

    auto load_chunk = [&](int s) {
        int p = s & 1;
        uint32_t sa  = sb + p * 32768;
        uint32_t sbb = sa + 16384;
        const __half* Ag = A + (size_t)m0 * K2c + s * 64;
        const __half* Wg = W + (size_t)n0 * K2c + s * 64;
        #pragma unroll
        for (int it = 0; it < 4; it++) {
            int e = it * 256 + t;
            int row = e >> 3, seg = e & 7;
            uint32_t sw = (uint32_t)((seg ^ (row & 7)) << 4);
            cpasync16(sa  + row * 128 + sw, Ag + (size_t)row * K2c + seg * 8);
            cpasync16(sbb + row * 128 + sw, Wg + (size_t)row * K2c + seg * 8);
        }
        asm volatile("cp.async.commit_group;");
    };

    load_chunk(0);

    for (int s = 0; s < NCH; s++) {
        if (s + 1 < NCH) {
            load_chunk(s + 1);
            asm volatile("cp.async.wait_group 1;");
        } else {
            asm volatile("cp.async.wait_group 0;");
        }
        __syncthreads();

        int p = s & 1;
        uint32_t sa  = sb + p * 32768;
        uint32_t sbb = sa + 16384;
        #pragma unroll
        for (int k2 = 0; k2 < 4; k2++) {
            uint32_t areg[2][4];
            #pragma unroll
            for (int i = 0; i < 2; i++)
                ldsm4(areg[i], sa + aoff[i] + ((((uint32_t)(k2*2 + khalf)) ^ asw[i]) << 4));
            uint32_t breg[4][4];
            #pragma unroll
            for (int pr = 0; pr < 4; pr++)
                ldsm4(breg[pr], sbb + boff[pr] + ((((uint32_t)(k2*2 + khalf)) ^ bsw[pr]) << 4));
            #pragma unroll
            for (int i = 0; i < 2; i++)
                #pragma unroll
                for (int j = 0; j < 8; j++)
                    mma16816h(acc[i][j], areg[i],
                              breg[j >> 1][j & 1], breg[j >> 1][2 + (j & 1)]);
        }
        __syncthreads();
    }

    const int r = l >> 2, q = l & 3;
    #pragma unroll
    for (int i = 0; i < 2; i++) {
        int row = m0 + wm + i * 16 + r;
        #pragma unroll
        for (int j = 0; j < 8; j++) {
            int col = n0 + wn + j * 8 + q * 2;
            float b0 = bias[col], b1 = bias[col + 1];
            *(float2*)(C + (size_t)row * 1024 + col) =
                make_float2(acc[i][j][0] + b0, acc[i][j][1] + b1);
            *(float2*)(C + (size_t)(row + 8) * 1024 + col) =
                make_float2(acc[i][j][2] + b0, acc[i][j][3] + b1);
        }
    }
}

// ===========================================================================
// SIMT SGEMM, 128x128 tiles (R11 config): C = A @ op(W) + bias
// modeW: 0 -> W [N,K] row-major (A@W^T);  1 -> W [K,N] row-major (A@W)
// modeA: 1 = gather rows via sidx; modeC: 1 = scatter rows to b*L+NT+q
// ===========================================================================
__global__ void __launch_bounds__(256)
sgemm_bias(const float* __restrict__ A, const float* __restrict__ W,
           const float* __restrict__ bias, float* __restrict__ C,
           int M, int N, int K,
           int modeA, const int* __restrict__ sidx, int modeC, int modeW)
{
    __shared__ float As[8][128];
    __shared__ float Bs[8][128];
    const int t    = threadIdx.x;
    const int row0 = blockIdx.y * 128;
    const int col0 = blockIdx.x * 128;
    const int a_r = t >> 1;
    const int a_c = (t & 1) << 2;
    int arow = row0 + a_r;
    size_t a_base;
    if (modeA == 1) {
        int bi = arow >> 6, qq = arow & 63;
        a_base = ((size_t)bi * Ll + (size_t)sidx[qq]) * (size_t)K;
    } else {
        a_base = (size_t)arow * (size_t)K;
    }
    const size_t w_base = (size_t)(col0 + a_r) * (size_t)K;
    const int kk2 = t >> 5;
    const int n4  = (t & 31) << 2;
    const int tr = (t >> 4) << 3;
    const int tc = (t & 15) << 3;
    float acc[8][8];
    #pragma unroll
    for (int i = 0; i < 8; i++)
        #pragma unroll
        for (int j = 0; j < 8; j++) acc[i][j] = 0.0f;
    for (int k0 = 0; k0 < K; k0 += 8) {
        float4 av = *(const float4*)(A + a_base + k0 + a_c);
        As[a_c+0][a_r] = av.x; As[a_c+1][a_r] = av.y;
        As[a_c+2][a_r] = av.z; As[a_c+3][a_r] = av.w;
        if (modeW == 0) {
            float4 wv = *(const float4*)(W + w_base + k0 + a_c);
            Bs[a_c+0][a_r] = wv.x; Bs[a_c+1][a_r] = wv.y;
            Bs[a_c+2][a_r] = wv.z; Bs[a_c+3][a_r] = wv.w;
        } else {
            float4 wv = *(const float4*)(W + (size_t)(k0 + kk2) * N + col0 + n4);
            *(float4*)&Bs[kk2][n4] = wv;
        }
        __syncthreads();
        #pragma unroll
        for (int k = 0; k < 8; k++) {
            float ra[8], rb[8];
            *(float4*)&ra[0] = *(const float4*)&As[k][tr];
            *(float4*)&ra[4] = *(const float4*)&As[k][tr+4];
            *(float4*)&rb[0] = *(const float4*)&Bs[k][tc];
            *(float4*)&rb[4] = *(const float4*)&Bs[k][tc+4];
            #pragma unroll
            for (int i = 0; i < 8; i++)
                #pragma unroll
                for (int j = 0; j < 8; j++)
                    acc[i][j] = fmaf(ra[i], rb[j], acc[i][j]);
        }
        __syncthreads();
    }
    #pragma unroll
    for (int i = 0; i < 8; i++) {
        int r = row0 + tr + i;
        int orow = (modeC == 1) ? ((r >> 6) * Ll + NTt + (r & 63)) : r;
        float* cp = C + (size_t)orow * (size_t)N + col0 + tc;
        #pragma unroll
        for (int j = 0; j < 8; j++)
            cp[j] = acc[i][j] + bias[col0 + tc + j];
    }
}

// ===========================================================================
// Temporal block attention (parallel softmax: 4 threads/row)
// ===========================================================================
#define TA_SMEM ((4160 + 8704 + 8448 + 128) * 4)

__global__ void __launch_bounds__(256)
temporal_attn(const float* __restrict__ Q, const float* __restrict__ K,
              const float* __restrict__ V,
              const int* __restrict__ tidx, const int* __restrict__ sidx,
              const float* __restrict__ tpm, const float* __restrict__ spm,
              float* __restrict__ out)
{
    const int h = blockIdx.x, nb = blockIdx.y, b = blockIdx.z;
    const int t = threadIdx.x;
    extern __shared__ float smf[];
    float* sqT   = smf;
    float* skv   = smf + 4160;
    float* sp    = skv + 8704;
    float* sbias = sp + 8448;

    if (t < 128) {
        float mk = (t < 64) ? tpm[((b*NBb)+nb)*BLb + t] : spm[b*NSs + (t-64)];
        sbias[t] = (mk == 1.0f) ? 0.0f : -1e30f;
    }
    for (int e = t; e < 64*64; e += 256) {
        int r = e >> 6, k = e & 63;
        int grow = tidx[nb*64 + r];
        sqT[k*65 + r] = Q[((size_t)b*Ll + grow)*Dd + h*64 + k];
    }
    for (int e = t; e < 128*64; e += 256) {
        int r = e >> 6, k = e & 63;
        int grow = (r < 64) ? tidx[nb*64 + r] : sidx[r - 64];
        skv[k*132 + r] = K[((size_t)b*Ll + grow)*Dd + h*64 + k];
    }
    __syncthreads();
    {
        const int r0 = (t >> 4) << 2;
        const int c0 = (t & 15) << 3;
        float acc[4][8];
        #pragma unroll
        for (int i = 0; i < 4; i++)
            #pragma unroll
            for (int j = 0; j < 8; j++) acc[i][j] = 0.0f;
        for (int k = 0; k < 64; k++) {
            float ra[4], rb[8];
            #pragma unroll
            for (int i = 0; i < 4; i++) ra[i] = sqT[k*65 + r0 + i];
            *(float4*)&rb[0] = *(const float4*)&skv[k*132 + c0];
            *(float4*)&rb[4] = *(const float4*)&skv[k*132 + c0 + 4];
            #pragma unroll
            for (int i = 0; i < 4; i++)
                #pragma unroll
                for (int j = 0; j < 8; j++)
                    acc[i][j] = fmaf(ra[i], rb[j], acc[i][j]);
        }
        #pragma unroll
        for (int i = 0; i < 4; i++)
            #pragma unroll
            for (int j = 0; j < 8; j++)
                sp[(r0+i)*132 + c0 + j] = acc[i][j]*0.125f + sbias[c0 + j];
    }
    __syncthreads();
    for (int e = t; e < 128*64; e += 256) {
        int r = e >> 6, k = e & 63;
        int grow = (r < 64) ? tidx[nb*64 + r] : sidx[r - 64];
        skv[r*68 + k] = V[((size_t)b*Ll + grow)*Dd + h*64 + k];
    }
    // parallel softmax: 4 threads per row
    {
        const int row = t >> 2, lane4 = t & 3;
        float* rp = sp + row*132;
        float mx = -1e30f;
        for (int c = lane4; c < 128; c += 4) mx = fmaxf(mx, rp[c]);
        mx = fmaxf(mx, __shfl_xor_sync(0xFFFFFFFFu, mx, 1));
        mx = fmaxf(mx, __shfl_xor_sync(0xFFFFFFFFu, mx, 2));
        float s = 0.0f;
        for (int c = lane4; c < 128; c += 4) { float p = __expf(rp[c]-mx); rp[c] = p; s += p; }
        s += __shfl_xor_sync(0xFFFFFFFFu, s, 1);
        s += __shfl_xor_sync(0xFFFFFFFFu, s, 2);
        float inv = 1.0f / s;
        for (int c = lane4; c < 128; c += 4) rp[c] *= inv;
    }
    __syncthreads();
    {
        const int r0 = (t >> 4) << 2;
        const int c0 = (t & 15) << 2;
        float acc[4][4];
        #pragma unroll
        for (int i = 0; i < 4; i++)
            #pragma unroll
            for (int j = 0; j < 4; j++) acc[i][j] = 0.0f;
        for (int j = 0; j < 128; j++) {
            float ra[4], rb[4];
            #pragma unroll
            for (int i = 0; i < 4; i++) ra[i] = sp[(r0+i)*132 + j];
            *(float4*)&rb[0] = *(const float4*)&skv[j*68 + c0];
            #pragma unroll
            for (int i = 0; i < 4; i++)
                #pragma unroll
                for (int jj = 0; jj < 4; jj++)
                    acc[i][jj] = fmaf(ra[i], rb[jj], acc[i][jj]);
        }
        #pragma unroll
        for (int i = 0; i < 4; i++)
            #pragma unroll
            for (int jj = 0; jj < 4; jj++)
                out[((size_t)b*Ll + nb*64 + r0 + i)*Dd + h*64 + c0 + jj] = acc[i][jj];
    }
}

// ===========================================================================
// Static attention (flash-style, parallel softmax)
// ===========================================================================
#define SA_SMEM ((4160 + 4352 + 4352 + 4352 + 256) * 4)

__global__ void __launch_bounds__(256)
static_attn(const float* __restrict__ Qs, const float* __restrict__ K2,
            const float* __restrict__ V2,
            const int* __restrict__ tidx, const int* __restrict__ sidx,
            const float* __restrict__ tpm, const float* __restrict__ spm,
            float* __restrict__ S)
{
    const int h = blockIdx.x, b = blockIdx.y;
    const int t = threadIdx.x;
    extern __shared__ float smf[];
    float* sqT  = smf;
    float* skT  = smf + 4160;
    float* sv   = skT + 4352;
    float* sp   = sv + 4352;
    float* mrow = sp + 4352;
    float* lrow = mrow + 64;
    float* arow = lrow + 64;
    float* sb2  = arow + 64;

    for (int e = t; e < 4096; e += 256) {
        int r = e >> 6, k = e & 63;
        sqT[k*65 + r] = Qs[((size_t)b*64 + r)*Dd + h*64 + k];
    }
    if (t < 64) { mrow[t] = -1e30f; lrow[t] = 0.0f; }

    const int r0 = (t >> 4) << 2;
    const int c0 = (t & 15) << 2;
    float O[4][4];
    #pragma unroll
    for (int i = 0; i < 4; i++)
        #pragma unroll
        for (int j = 0; j < 4; j++) O[i][j] = 0.0f;

    for (int jc = 0; jc < 65; jc++) {
        int base = jc * 64;
        __syncthreads();
        for (int e = t; e < 4096; e += 256) {
            int j = e >> 6, k = e & 63;
            int jj = base + j;
            int grow = (jj < NTt) ? tidx[jj] : sidx[jj - NTt];
            size_t gb = ((size_t)b*Ll + grow)*Dd + h*64 + k;
            skT[k*68 + j] = K2[gb];
            sv[j*68 + k]  = V2[gb];
        }
        if (t < 64) {
            int jj = base + t;
            float mk = (jj < NTt) ? tpm[b*NTt + jj] : spm[b*NSs + (jj - NTt)];
            sb2[t] = (mk == 1.0f) ? 0.0f : -1e30f;
        }
        __syncthreads();

        float acc[4][4];
        #pragma unroll
        for (int i = 0; i < 4; i++)
            #pragma unroll
            for (int j = 0; j < 4; j++) acc[i][j] = 0.0f;
        for (int k = 0; k < 64; k++) {
            float ra[4], rb[4];
            #pragma unroll
            for (int i = 0; i < 4; i++) ra[i] = sqT[k*65 + r0 + i];
            *(float4*)&rb[0] = *(const float4*)&skT[k*68 + c0];
            #pragma unroll
            for (int i = 0; i < 4; i++)
                #pragma unroll
                for (int j = 0; j < 4; j++)
                    acc[i][j] = fmaf(ra[i], rb[j], acc[i][j]);
        }
        #pragma unroll
        for (int i = 0; i < 4; i++)
            #pragma unroll
            for (int j = 0; j < 4; j++)
                sp[(r0+i)*68 + c0 + j] = acc[i][j]*0.125f + sb2[c0 + j];
        __syncthreads();

        // parallel running softmax: 4 threads per row
        {
            const int row = t >> 2, lane4 = t & 3;
            float* rp = sp + row*68;
            float mold = mrow[row];
            float mx = mold;
            for (int c = lane4; c < 64; c += 4) mx = fmaxf(mx, rp[c]);
            mx = fmaxf(mx, __shfl_xor_sync(0xFFFFFFFFu, mx, 1));
            mx = fmaxf(mx, __shfl_xor_sync(0xFFFFFFFFu, mx, 2));
            float a = __expf(mold - mx);
            float ssum = 0.0f;
            for (int c = lane4; c < 64; c += 4) { float p = __expf(rp[c]-mx); rp[c] = p; ssum += p; }
            ssum += __shfl_xor_sync(0xFFFFFFFFu, ssum, 1);
            ssum += __shfl_xor_sync(0xFFFFFFFFu, ssum, 2);
            if (lane4 == 0) {
                lrow[row] = lrow[row]*a + ssum;
                mrow[row] = mx;
                arow[row] = a;
            }
        }
        __syncthreads();
        {
            float al[4];
            #pragma unroll
            for (int i = 0; i < 4; i++) al[i] = arow[r0 + i];
            float acc2[4][4];
            #pragma unroll
            for (int i = 0; i < 4; i++)
                #pragma unroll
                for (int j = 0; j < 4; j++) acc2[i][j] = 0.0f;
            for (int j = 0; j < 64; j++) {
                float ra[4], rb[4];
                #pragma unroll
                for (int i = 0; i < 4; i++) ra[i] = sp[(r0+i)*68 + j];
                *(float4*)&rb[0] = *(const float4*)&sv[j*68 + c0];
                #pragma unroll
                for (int i = 0; i < 4; i++)
                    #pragma unroll
                    for (int jj = 0; jj < 4; jj++)
                        acc2[i][jj] = fmaf(ra[i], rb[jj], acc2[i][jj]);
            }
            #pragma unroll
            for (int i = 0; i < 4; i++)
                #pragma unroll
                for (int j = 0; j < 4; j++)
                    O[i][j] = O[i][j]*al[i] + acc2[i][j];
        }
    }
    #pragma unroll
    for (int i = 0; i < 4; i++) {
        float inv = 1.0f / lrow[r0 + i];
        #pragma unroll
        for (int j = 0; j < 4; j++)
            S[((size_t)b*64 + r0 + i)*Dd + h*64 + c0 + j] = O[i][j]*inv;
    }
}

// ===========================================================================
extern "C" void kernel_launch(void* const* d_in, const int* in_sizes, int n_in,
                              void* d_out, int out_size)
{
    (void)in_sizes; (void)out_size;
    const float* query = (const float*)d_in[0];
    const float* key   = (const float*)d_in[1];
    const float* value = (const float*)d_in[2];
    const int*   tidx  = (const int*)  d_in[3];
    const int*   sidx  = (const int*)  d_in[4];
    const float* tpm   = (const float*)d_in[5];
    const float* spm   = (const float*)d_in[6];
    const float* outb  = (const float*)d_in[n_in-1];
    const float* outw  = (const float*)d_in[n_in-2];
    const float* ipb   = (const float*)d_in[n_in-3];
    const float* ipw   = (const float*)d_in[n_in-4];
    const float* bv    = (const float*)d_in[n_in-5];
    const float* Wv    = (const float*)d_in[n_in-6];
    const float* bk    = (const float*)d_in[n_in-7];
    const float* Wk    = (const float*)d_in[n_in-8];
    const float* bq    = (const float*)d_in[n_in-9];
    const float* Wq    = (const float*)d_in[n_in-10];
    float* out = (float*)d_out;

    float *Q, *K, *V, *K2p, *V2p, *QS, *S, *Wcomb, *bck, *bcv, *zero;
    __half *Xq, *Xk, *Xv, *Wc;
    cudaGetSymbolAddress((void**)&Q,  g_Q);
    cudaGetSymbolAddress((void**)&K,  g_K);
    cudaGetSymbolAddress((void**)&V,  g_V);
    cudaGetSymbolAddress((void**)&K2p, g_K2);
    cudaGetSymbolAddress((void**)&V2p, g_V2);
    cudaGetSymbolAddress((void**)&QS, g_QS);
    cudaGetSymbolAddress((void**)&S,  g_S);
    cudaGetSymbolAddress((void**)&Xq, g_Xq);
    cudaGetSymbolAddress((void**)&Xk, g_Xk);
    cudaGetSymbolAddress((void**)&Xv, g_Xv);
    cudaGetSymbolAddress((void**)&Wc, g_Wc);
    cudaGetSymbolAddress((void**)&Wcomb, g_Wcomb);
    cudaGetSymbolAddress((void**)&bck, g_bck);
    cudaGetSymbolAddress((void**)&bcv, g_bcv);
    cudaGetSymbolAddress((void**)&zero, g_zero);

    cudaFuncSetAttribute(gemm_fp16,     cudaFuncAttributeMaxDynamicSharedMemorySize, GB_SMEM);
    cudaFuncSetAttribute(temporal_attn, cudaFuncAttributeMaxDynamicSharedMemorySize, TA_SMEM);
    cudaFuncSetAttribute(static_attn,   cudaFuncAttributeMaxDynamicSharedMemorySize, SA_SMEM);

    static cudaStream_t s2 = 0, s3 = 0;
    static cudaEvent_t ev0 = 0, evQx = 0, evKx = 0, evVx = 0, evQKV = 0,
                       evQS = 0, evS2 = 0, evWc = 0;
    if (!s2) {
        cudaStreamCreateWithFlags(&s2, cudaStreamNonBlocking);
        cudaStreamCreateWithFlags(&s3, cudaStreamNonBlocking);
        cudaEventCreateWithFlags(&ev0,   cudaEventDisableTiming);
        cudaEventCreateWithFlags(&evQx,  cudaEventDisableTiming);
        cudaEventCreateWithFlags(&evKx,  cudaEventDisableTiming);
        cudaEventCreateWithFlags(&evVx,  cudaEventDisableTiming);
        cudaEventCreateWithFlags(&evQKV, cudaEventDisableTiming);
        cudaEventCreateWithFlags(&evQS,  cudaEventDisableTiming);
        cudaEventCreateWithFlags(&evS2,  cudaEventDisableTiming);
        cudaEventCreateWithFlags(&evWc,  cudaEventDisableTiming);
    }

    dim3 blk(256);
    dim3 ggemm(Dd/128, Mtot/128);          // (8, 260)
    dim3 gsq(Dd/128, Dd/128);              // (8, 8)
    dim3 gsm(Dd/128, (Bb*NSs)/128);        // (8, 4)
    const int wn4 = Dd*Dd/4;
    const int xn4 = Mtot*Dd/4;
    const int wblocks = (wn4 + 255)/256;
    const int xblocks = (xn4 + 255)/256;
    __half* Wc0 = Wc;
    __half* Wc1 = Wc + (size_t)1*Dd*K2c;
    __half* Wc2 = Wc + (size_t)2*Dd*K2c;
    __half* Wc3 = Wc + (size_t)3*Dd*K2c;
    __half* Wc4 = Wc + (size_t)4*Dd*K2c;
    float* Wcombk = Wcomb;
    float* Wcombv = Wcomb + (size_t)Dd*Dd;
    const float* Wk2 = ipw + (size_t)Dd*Dd;
    const float* Wv2 = ipw + (size_t)2*Dd*Dd;

    cudaEventRecord(ev0, 0);

    // ---- fork s2: input/weight fp16 conversions (hi-only) ----
    cudaStreamWaitEvent(s2, ev0, 0);
    conv_hi<<<wblocks, blk, 0, s2>>>(Wq, Wc0, wn4);
    conv_hi<<<xblocks, blk, 0, s2>>>(query, Xq, xn4);
    cudaEventRecord(evQx, s2);
    conv_hi<<<wblocks, blk, 0, s2>>>(Wk, Wc1, wn4);
    conv_hi<<<xblocks, blk, 0, s2>>>(key, Xk, xn4);
    cudaEventRecord(evKx, s2);
    conv_hi<<<wblocks, blk, 0, s2>>>(Wv, Wc2, wn4);
    conv_hi<<<xblocks, blk, 0, s2>>>(value, Xv, xn4);
    cudaEventRecord(evVx, s2);

    // ---- fork s3: weight-combine chain (needed only by K2/V2 GEMMs) ----
    cudaStreamWaitEvent(s3, ev0, 0);
    sgemm_bias<<<gsq, blk, 0, s3>>>(Wk2, Wk, zero, Wcombk, Dd, Dd, Dd, 0, sidx, 0, 1);
    sgemm_bias<<<gsq, blk, 0, s3>>>(Wv2, Wv, zero, Wcombv, Dd, Dd, Dd, 0, sidx, 0, 1);
    bias_comb<<<Dd, blk, 0, s3>>>(Wk2, bk, ipb + Dd,   bck);
    bias_comb<<<Dd, blk, 0, s3>>>(Wv2, bv, ipb + 2*Dd, bcv);
    conv_hi<<<wblocks, blk, 0, s3>>>(Wcombk, Wc3, wn4);
    conv_hi<<<wblocks, blk, 0, s3>>>(Wcombv, Wc4, wn4);
    cudaEventRecord(evWc, s3);

    // ---- main: Q/K/V GEMMs (single-term fp16, K=1024) ----
    cudaStreamWaitEvent(0, evQx, 0);
    gemm_fp16<<<ggemm, blk, GB_SMEM>>>(Xq, Wc0, bq, Q, 16);
    cudaStreamWaitEvent(0, evKx, 0);
    gemm_fp16<<<ggemm, blk, GB_SMEM>>>(Xk, Wc1, bk, K, 16);
    cudaStreamWaitEvent(0, evVx, 0);
    gemm_fp16<<<ggemm, blk, GB_SMEM>>>(Xv, Wc2, bv, V, 16);
    cudaEventRecord(evQKV, 0);

    // ---- fork s2: QS proj -> (evQS) -> temporal attention
    //      main: K2/V2 GEMMs (after evWc) -> static attention ----
    cudaStreamWaitEvent(s2, evQKV, 0);
    sgemm_bias<<<gsm, blk, 0, s2>>>(Q, ipw, ipb, QS, Bb*NSs, Dd, Dd, 1, sidx, 0, 0);
    cudaEventRecord(evQS, s2);
    temporal_attn<<<dim3(Hh, NBb, Bb), blk, TA_SMEM, s2>>>(Q, K, V, tidx, sidx, tpm, spm, out);
    cudaEventRecord(evS2, s2);

    cudaStreamWaitEvent(0, evWc, 0);
    gemm_fp16<<<ggemm, blk, GB_SMEM>>>(Xk, Wc3, bck, K2p, 16);
    gemm_fp16<<<ggemm, blk, GB_SMEM>>>(Xv, Wc4, bcv, V2p, 16);

    cudaStreamWaitEvent(0, evQS, 0);
    static_attn<<<dim3(Hh, Bb), blk, SA_SMEM>>>(QS, K2p, V2p, tidx, sidx, tpm, spm, S);
    sgemm_bias<<<gsm, blk>>>(S, outw, outb, out, Bb*NSs, Dd, Dd, 0, sidx, 1, 0);

    // join temporal branch back into main stream (capture requires rejoin)
    cudaStreamWaitEvent(0, evS2, 0);
}

// round 14
// speedup vs baseline: 1.2872x; 1.1377x over previous
#include <cuda_runtime.h>
#include <cuda_fp16.h>
#include <cstdint>
#include <cstddef>

// Problem constants
#define Bb   8
#define Ll   4160
#define Dd   1024
#define Hh   16
#define NBb  64
#define BLb  64
#define NSs  64
#define NTt  4096   // NB*BL
#define Mtot (Bb*Ll)      // 33280
#define K2c  2048         // row stride of fp16 operand buffers (only [0,1024) used)

// Scratch (device globals: allocation-free)
__device__ float g_Q [(size_t)Mtot*Dd];
__device__ float g_K [(size_t)Mtot*Dd];
__device__ float g_V [(size_t)Mtot*Dd];
__device__ float g_K2[(size_t)Mtot*Dd];
__device__ float g_V2[(size_t)Mtot*Dd];
__device__ float g_QS[(size_t)Bb*NSs*Dd];
__device__ float g_S [(size_t)Bb*NSs*Dd];
__device__ __half g_Xq[(size_t)Mtot*K2c];
__device__ __half g_Xk[(size_t)Mtot*K2c];
__device__ __half g_Xv[(size_t)Mtot*K2c];
__device__ __half g_Wc[5][(size_t)Dd*K2c];
__device__ float g_Wcomb[2][(size_t)Dd*Dd];
__device__ float g_bck[Dd];
__device__ float g_bcv[Dd];
__device__ float g_zero[Dd];   // zero-initialized, never written

// ===========================================================================
// helpers
// ===========================================================================
__device__ __forceinline__ uint32_t smem_u32(const void* p) {
    uint32_t a;
    asm("{ .reg .u64 t; cvta.to.shared.u64 t, %1; cvt.u32.u64 %0, t; }"
        : "=r"(a) : "l"(p));
    return a;
}
__device__ __forceinline__ void ldsm4(uint32_t* r, uint32_t addr) {
    asm volatile("ldmatrix.sync.aligned.m8n8.x4.shared.b16 {%0,%1,%2,%3}, [%4];"
                 : "=r"(r[0]), "=r"(r[1]), "=r"(r[2]), "=r"(r[3]) : "r"(addr));
}
__device__ __forceinline__ void mma16816h(float* d, const uint32_t* a,
                                          uint32_t b0, uint32_t b1) {
    asm volatile("mma.sync.aligned.m16n8k16.row.col.f32.f16.f16.f32 "
                 "{%0,%1,%2,%3}, {%4,%5,%6,%7}, {%8,%9}, {%0,%1,%2,%3};"
                 : "+f"(d[0]), "+f"(d[1]), "+f"(d[2]), "+f"(d[3])
                 : "r"(a[0]), "r"(a[1]), "r"(a[2]), "r"(a[3]), "r"(b0), "r"(b1));
}
__device__ __forceinline__ void cpasync16(uint32_t d, const void* g) {
    asm volatile("cp.async.cg.shared.global [%0], [%1], 16;" :: "r"(d), "l"(g));
}
__device__ __forceinline__ uint32_t packh2(__half a, __half b) {
    __half2 p = __halves2half2(a, b);
    return *(uint32_t*)&p;
}

// ===========================================================================
// Convert X fp32 [rows x 1024] -> Y fp16 hi-only (row stride K2c).
// ===========================================================================
__global__ void __launch_bounds__(256)
conv_hi(const float* __restrict__ X, __half* __restrict__ Y, int n4)
{
    int i = blockIdx.x * blockDim.x + threadIdx.x;
    if (i >= n4) return;
    float4 v = ((const float4*)X)[i];
    int e = i << 2;
    int row = e >> 10, col = e & 1023;
    uint2 hv = make_uint2(packh2(__float2half_rn(v.x), __float2half_rn(v.y)),
                          packh2(__float2half_rn(v.z), __float2half_rn(v.w)));
    *(uint2*)(Y + (size_t)row * K2c + col) = hv;
}

// ===========================================================================
// bias combine: out[i] = dot(W2 row i, b1) + b2[i].  grid = 1024 blocks.
// ===========================================================================
__global__ void __launch_bounds__(256)
bias_comb(const float* __restrict__ W2, const float* __restrict__ b1,
          const float* __restrict__ b2, float* __restrict__ out)
{
    __shared__ float red[256];
    int i = blockIdx.x;
    float s = 0.0f;
    for (int k = threadIdx.x; k < Dd; k += 256)
        s += W2[(size_t)i * Dd + k] * b1[k];
    red[threadIdx.x] = s;
    __syncthreads();
    for (int st = 128; st > 0; st >>= 1) {
        if (threadIdx.x < st) red[threadIdx.x] += red[threadIdx.x + st];
        __syncthreads();
    }
    if (threadIdx.x == 0) out[i] = red[0] + b2[i];
}

// ===========================================================================
// fp16 TN GEMM (2 CTA/SM): C[M,1024] = A'[M,:64*kchunks] @ W'[1024,...]^T
// ===========================================================================
#define GB_SMEM (2*32768)

__global__ void __launch_bounds__(256)
gemm_fp16(const __half* __restrict__ A, const __half* __restrict__ W,
          const float* __restrict__ bias, float* __restrict__ C, int kchunks)
{
    extern __shared__ char gsm[];
    const uint32_t sb = smem_u32(gsm);
    const int t = threadIdx.x;
    const int m0 = blockIdx.y * 128;
    const int n0 = blockIdx.x * 128;

    const int l = t & 31, wid = t >> 5;
    const int wm = (wid & 3) * 32;
    const int wn = (wid >> 2) * 64;
    const int lr = (l & 7) + ((l >> 3) & 1) * 8;
    const int khalf = l >> 4;

    uint32_t aoff[2], asw[2];
    #pragma unroll
    for (int i = 0; i < 2; i++) {
        int row = wm + i * 16 + lr;
        aoff[i] = row * 128;
        asw[i]  = row & 7;
    }
    uint32_t boff[4], bsw[4];
    #pragma unroll
    for (int pr = 0; pr < 4; pr++) {
        int row = wn + pr * 16 + lr;
        boff[pr] = row * 128;
        bsw[pr]  = row & 7;
    }

    float acc[2][8][4];
    #pragma unroll
    for (int i = 0; i < 2; i++)
        #pragma unroll
        for (int j = 0; j < 8; j++)
            #pragma unroll
            for (int z = 0; z < 4; z++) acc[i][j][z] = 0.0f;

    const int NCH = kchunks;

    auto load_chunk = [&](int s) {
        int p = s & 1;
        uint32_t sa  = sb + p * 32768;
        uint32_t sbb = sa + 16384;
        const __half* Ag = A + (size_t)m0 * K2c + s * 64;
        const __half* Wg = W + (size_t)n0 * K2c + s * 64;
        #pragma unroll
        for (int it = 0; it < 4; it++) {
            int e = it * 256 + t;
            int row = e >> 3, seg = e & 7;
            uint32_t sw = (uint32_t)((seg ^ (row & 7)) << 4);
            cpasync16(sa  + row * 128 + sw, Ag + (size_t)row * K2c + seg * 8);
            cpasync16(sbb + row * 128 + sw, Wg + (size_t)row * K2c + seg * 8);
        }
        asm volatile("cp.async.commit_group;");
    };

    load_chunk(0);

    for (int s = 0; s < NCH; s++) {
        if (s + 1 < NCH) {
            load_chunk(s + 1);
            asm volatile("cp.async.wait_group 1;");
        } else {
            asm volatile("cp.async.wait_group 0;");
        }
        __syncthreads();

        int p = s & 1;
        uint32_t sa  = sb + p * 32768;
        uint32_t sbb = sa + 16384;
        #pragma unroll
        for (int k2 = 0; k2 < 4; k2++) {
            uint32_t areg[2][4];
            #pragma unroll
            for (int i = 0; i < 2; i++)
                ldsm4(areg[i], sa + aoff[i] + ((((uint32_t)(k2*2 + khalf)) ^ asw[i]) << 4));
            uint32_t breg[4][4];
            #pragma unroll
            for (int pr = 0; pr < 4; pr++)
                ldsm4(breg[pr], sbb + boff[pr] + ((((uint32_t)(k2*2 + khalf)) ^ bsw[pr]) << 4));
            #pragma unroll
            for (int i = 0; i < 2; i++)
                #pragma unroll
                for (int j = 0; j < 8; j++)
                    mma16816h(acc[i][j], areg[i],
                              breg[j >> 1][j & 1], breg[j >> 1][2 + (j & 1)]);
        }
        __syncthreads();
    }

    const int r = l >> 2, q = l & 3;
    #pragma unroll
    for (int i = 0; i < 2; i++) {
        int row = m0 + wm + i * 16 + r;
        #pragma unroll
        for (int j = 0; j < 8; j++) {
            int col = n0 + wn + j * 8 + q * 2;
            float b0 = bias[col], b1 = bias[col + 1];
            *(float2*)(C + (size_t)row * 1024 + col) =
                make_float2(acc[i][j][0] + b0, acc[i][j][1] + b1);
            *(float2*)(C + (size_t)(row + 8) * 1024 + col) =
                make_float2(acc[i][j][2] + b0, acc[i][j][3] + b1);
        }
    }
}

// ===========================================================================
// SIMT SGEMM, 128x128 tiles: C = A @ op(W) + bias
// modeW: 0 -> W [N,K] row-major (A@W^T);  1 -> W [K,N] row-major (A@W)
// modeA: 1 = gather rows via sidx; modeC: 1 = scatter rows to b*L+NT+q
// ===========================================================================
__global__ void __launch_bounds__(256)
sgemm_bias(const float* __restrict__ A, const float* __restrict__ W,
           const float* __restrict__ bias, float* __restrict__ C,
           int M, int N, int K,
           int modeA, const int* __restrict__ sidx, int modeC, int modeW)
{
    __shared__ float As[8][128];
    __shared__ float Bs[8][128];
    const int t    = threadIdx.x;
    const int row0 = blockIdx.y * 128;
    const int col0 = blockIdx.x * 128;
    const int a_r = t >> 1;
    const int a_c = (t & 1) << 2;
    int arow = row0 + a_r;
    size_t a_base;
    if (modeA == 1) {
        int bi = arow >> 6, qq = arow & 63;
        a_base = ((size_t)bi * Ll + (size_t)sidx[qq]) * (size_t)K;
    } else {
        a_base = (size_t)arow * (size_t)K;
    }
    const size_t w_base = (size_t)(col0 + a_r) * (size_t)K;
    const int kk2 = t >> 5;
    const int n4  = (t & 31) << 2;
    const int tr = (t >> 4) << 3;
    const int tc = (t & 15) << 3;
    float acc[8][8];
    #pragma unroll
    for (int i = 0; i < 8; i++)
        #pragma unroll
        for (int j = 0; j < 8; j++) acc[i][j] = 0.0f;
    for (int k0 = 0; k0 < K; k0 += 8) {
        float4 av = *(const float4*)(A + a_base + k0 + a_c);
        As[a_c+0][a_r] = av.x; As[a_c+1][a_r] = av.y;
        As[a_c+2][a_r] = av.z; As[a_c+3][a_r] = av.w;
        if (modeW == 0) {
            float4 wv = *(const float4*)(W + w_base + k0 + a_c);
            Bs[a_c+0][a_r] = wv.x; Bs[a_c+1][a_r] = wv.y;
            Bs[a_c+2][a_r] = wv.z; Bs[a_c+3][a_r] = wv.w;
        } else {
            float4 wv = *(const float4*)(W + (size_t)(k0 + kk2) * N + col0 + n4);
            *(float4*)&Bs[kk2][n4] = wv;
        }
        __syncthreads();
        #pragma unroll
        for (int k = 0; k < 8; k++) {
            float ra[8], rb[8];
            *(float4*)&ra[0] = *(const float4*)&As[k][tr];
            *(float4*)&ra[4] = *(const float4*)&As[k][tr+4];
            *(float4*)&rb[0] = *(const float4*)&Bs[k][tc];
            *(float4*)&rb[4] = *(const float4*)&Bs[k][tc+4];
            #pragma unroll
            for (int i = 0; i < 8; i++)
                #pragma unroll
                for (int j = 0; j < 8; j++)
                    acc[i][j] = fmaf(ra[i], rb[j], acc[i][j]);
        }
        __syncthreads();
    }
    #pragma unroll
    for (int i = 0; i < 8; i++) {
        int r = row0 + tr + i;
        int orow = (modeC == 1) ? ((r >> 6) * Ll + NTt + (r & 63)) : r;
        float* cp = C + (size_t)orow * (size_t)N + col0 + tc;
        #pragma unroll
        for (int j = 0; j < 8; j++)
            cp[j] = acc[i][j] + bias[col0 + tc + j];
    }
}

// ===========================================================================
// Temporal block attention — tensor-core version.
// QK^T (64x128x64) and PV (64x64x128) via mma.sync fp16, fp32 softmax.
// SMEM (conflict-free unswizzled, stride = data+16B):
//   sqh  64 x 72 halves (9216 B)
//   skh 128 x 72 halves (18432 B)
//   svT  64 x 136 halves (17408 B)  rows=d, cols=j  (V transposed)
//   sp16 64 x 136 halves (17408 B)  fp16 probabilities
//   sp   64 x 132 floats (33792 B)  fp32 logits
//   sbias 128 floats (512 B)
// ===========================================================================
#define TA_SMEM (62464 + 33792 + 512)

__global__ void __launch_bounds__(256)
temporal_attn(const float* __restrict__ Q, const float* __restrict__ K,
              const float* __restrict__ V,
              const int* __restrict__ tidx, const int* __restrict__ sidx,
              const float* __restrict__ tpm, const float* __restrict__ spm,
              float* __restrict__ out)
{
    const int h = blockIdx.x, nb = blockIdx.y, b = blockIdx.z;
    const int t = threadIdx.x;
    extern __shared__ char smc[];
    __half* sqh  = (__half*)smc;        // 64 x 72
    __half* skh  = sqh + 4608;          // 128 x 72
    __half* svT  = skh + 9216;          // 64 x 136
    __half* sp16 = svT + 8704;          // 64 x 136
    float*  sp   = (float*)(smc + 62464);
    float*  sbias= sp + 64*132;

    const uint32_t sqh_u  = smem_u32(sqh);
    const uint32_t skh_u  = smem_u32(skh);
    const uint32_t svT_u  = smem_u32(svT);
    const uint32_t sp16_u = smem_u32(sp16);

    if (t < 128) {
        float mk = (t < 64) ? tpm[((b*NBb)+nb)*BLb + t] : spm[b*NSs + (t-64)];
        sbias[t] = (mk == 1.0f) ? 0.0f : -1e30f;
    }
    for (int e = t; e < 64*64; e += 256) {
        int r = e >> 6, k = e & 63;
        int grow = tidx[nb*64 + r];
        sqh[r*72 + k] = __float2half_rn(Q[((size_t)b*Ll + grow)*Dd + h*64 + k]);
    }
    for (int e = t; e < 128*64; e += 256) {
        int r = e >> 6, k = e & 63;
        int grow = (r < 64) ? tidx[nb*64 + r] : sidx[r - 64];
        skh[r*72 + k] = __float2half_rn(K[((size_t)b*Ll + grow)*Dd + h*64 + k]);
    }
    for (int e = t; e < 128*64; e += 256) {
        int j = e >> 6, d = e & 63;
        int grow = (j < 64) ? tidx[nb*64 + j] : sidx[j - 64];
        svT[d*136 + j] = __float2half_rn(V[((size_t)b*Ll + grow)*Dd + h*64 + d]);
    }
    __syncthreads();

    const int l = t & 31, wid = t >> 5;
    const int lr = (l & 7) + ((l >> 3) & 1) * 8;
    const int khalf = l >> 4;
    const int rr = l >> 2, qq = l & 3;

    // ---- logits = Q @ K^T * scale + bias -> sp (fp32) ----
    {
        const int wm = (wid & 1) * 32;
        const int wn = (wid >> 1) * 32;
        float acc[2][4][4];
        #pragma unroll
        for (int i = 0; i < 2; i++)
            #pragma unroll
            for (int j = 0; j < 4; j++)
                #pragma unroll
                for (int z = 0; z < 4; z++) acc[i][j][z] = 0.0f;
        #pragma unroll
        for (int k2 = 0; k2 < 4; k2++) {
            const uint32_t kc = (uint32_t)(k2*2 + khalf);
            uint32_t areg[2][4], breg[2][4];
            #pragma unroll
            for (int i = 0; i < 2; i++)
                ldsm4(areg[i], sqh_u + (uint32_t)(wm + i*16 + lr)*144u + kc*16u);
            #pragma unroll
            for (int pr = 0; pr < 2; pr++)
                ldsm4(breg[pr], skh_u + (uint32_t)(wn + pr*16 + lr)*144u + kc*16u);
            #pragma unroll
            for (int i = 0; i < 2; i++)
                #pragma unroll
                for (int j = 0; j < 4; j++)
                    mma16816h(acc[i][j], areg[i],
                              breg[j >> 1][j & 1], breg[j >> 1][2 + (j & 1)]);
        }
        #pragma unroll
        for (int i = 0; i < 2; i++) {
            int row = wm + i*16 + rr;
            #pragma unroll
            for (int j = 0; j < 4; j++) {
                int col = wn + j*8 + qq*2;
                float b0 = sbias[col], b1 = sbias[col+1];
                sp[row*132 + col]       = acc[i][j][0]*0.125f + b0;
                sp[row*132 + col + 1]   = acc[i][j][1]*0.125f + b1;
                sp[(row+8)*132 + col]   = acc[i][j][2]*0.125f + b0;
                sp[(row+8)*132 + col+1] = acc[i][j][3]*0.125f + b1;
            }
        }
    }
    __syncthreads();

    // ---- parallel softmax (4 threads/row), emit fp16 copy ----
    {
        const int row = t >> 2, lane4 = t & 3;
        float* rp = sp + row*132;
        __half* rp16 = sp16 + row*136;
        float mx = -1e30f;
        for (int c = lane4; c < 128; c += 4) mx = fmaxf(mx, rp[c]);
        mx = fmaxf(mx, __shfl_xor_sync(0xFFFFFFFFu, mx, 1));
        mx = fmaxf(mx, __shfl_xor_sync(0xFFFFFFFFu, mx, 2));
        float s = 0.0f;
        for (int c = lane4; c < 128; c += 4) { float p = __expf(rp[c]-mx); rp[c] = p; s += p; }
        s += __shfl_xor_sync(0xFFFFFFFFu, s, 1);
        s += __shfl_xor_sync(0xFFFFFFFFu, s, 2);
        float inv = 1.0f / s;
        for (int c = lane4; c < 128; c += 4) rp16[c] = __float2half_rn(rp[c]*inv);
    }
    __syncthreads();

    // ---- out = P @ V  (A = sp16, B = svT) ----
    {
        const int wm = (wid & 1) * 32;
        const int wn = (wid >> 1) * 16;
        float acc[2][2][4];
        #pragma unroll
        for (int i = 0; i < 2; i++)
            #pragma unroll
            for (int j = 0; j < 2; j++)
                #pragma unroll
                for (int z = 0; z < 4; z++) acc[i][j][z] = 0.0f;
        #pragma unroll
        for (int k2 = 0; k2 < 8; k2++) {
            const uint32_t kc = (uint32_t)(k2*2 + khalf);
            uint32_t areg[2][4], breg[4];
            #pragma unroll
            for (int i = 0; i < 2; i++)
                ldsm4(areg[i], sp16_u + (uint32_t)(wm + i*16 + lr)*272u + kc*16u);
            ldsm4(breg, svT_u + (uint32_t)(wn + lr)*272u + kc*16u);
            #pragma unroll
            for (int i = 0; i < 2; i++)
                #pragma unroll
                for (int j = 0; j < 2; j++)
                    mma16816h(acc[i][j], areg[i], breg[j], breg[2 + j]);
        }
        #pragma unroll
        for (int i = 0; i < 2; i++) {
            int row = wm + i*16 + rr;
            #pragma unroll
            for (int j = 0; j < 2; j++) {
                int col = h*64 + wn + j*8 + qq*2;
                *(float2*)(out + ((size_t)b*Ll + nb*64 + row)*Dd + col) =
                    make_float2(acc[i][j][0], acc[i][j][1]);
                *(float2*)(out + ((size_t)b*Ll + nb*64 + row + 8)*Dd + col) =
                    make_float2(acc[i][j][2], acc[i][j][3]);
            }
        }
    }
}

// ===========================================================================
// Static attention (flash-style, parallel softmax) — SIMT
// ===========================================================================
#define SA_SMEM ((4160 + 4352 + 4352 + 4352 + 256) * 4)

__global__ void __launch_bounds__(256)
static_attn(const float* __restrict__ Qs, const float* __restrict__ K2,
            const float* __restrict__ V2,
            const int* __restrict__ tidx, const int* __restrict__ sidx,
            const float* __restrict__ tpm, const float* __restrict__ spm,
            float* __restrict__ S)
{
    const int h = blockIdx.x, b = blockIdx.y;
    const int t = threadIdx.x;
    extern __shared__ float smf[];
    float* sqT  = smf;
    float* skT  = smf + 4160;
    float* sv   = skT + 4352;
    float* sp   = sv + 4352;
    float* mrow = sp + 4352;
    float* lrow = mrow + 64;
    float* arow = lrow + 64;
    float* sb2  = arow + 64;

    for (int e = t; e < 4096; e += 256) {
        int r = e >> 6, k = e & 63;
        sqT[k*65 + r] = Qs[((size_t)b*64 + r)*Dd + h*64 + k];
    }
    if (t < 64) { mrow[t] = -1e30f; lrow[t] = 0.0f; }

    const int r0 = (t >> 4) << 2;
    const int c0 = (t & 15) << 2;
    float O[4][4];
    #pragma unroll
    for (int i = 0; i < 4; i++)
        #pragma unroll
        for (int j = 0; j < 4; j++) O[i][j] = 0.0f;

    for (int jc = 0; jc < 65; jc++) {
        int base = jc * 64;
        __syncthreads();
        for (int e = t; e < 4096; e += 256) {
            int j = e >> 6, k = e & 63;
            int jj = base + j;
            int grow = (jj < NTt) ? tidx[jj] : sidx[jj - NTt];
            size_t gb = ((size_t)b*Ll + grow)*Dd + h*64 + k;
            skT[k*68 + j] = K2[gb];
            sv[j*68 + k]  = V2[gb];
        }
        if (t < 64) {
            int jj = base + t;
            float mk = (jj < NTt) ? tpm[b*NTt + jj] : spm[b*NSs + (jj - NTt)];
            sb2[t] = (mk == 1.0f) ? 0.0f : -1e30f;
        }
        __syncthreads();

        float acc[4][4];
        #pragma unroll
        for (int i = 0; i < 4; i++)
            #pragma unroll
            for (int j = 0; j < 4; j++) acc[i][j] = 0.0f;
        for (int k = 0; k < 64; k++) {
            float ra[4], rb[4];
            #pragma unroll
            for (int i = 0; i < 4; i++) ra[i] = sqT[k*65 + r0 + i];
            *(float4*)&rb[0] = *(const float4*)&skT[k*68 + c0];
            #pragma unroll
            for (int i = 0; i < 4; i++)
                #pragma unroll
                for (int j = 0; j < 4; j++)
                    acc[i][j] = fmaf(ra[i], rb[j], acc[i][j]);
        }
        #pragma unroll
        for (int i = 0; i < 4; i++)
            #pragma unroll
            for (int j = 0; j < 4; j++)
                sp[(r0+i)*68 + c0 + j] = acc[i][j]*0.125f + sb2[c0 + j];
        __syncthreads();

        {
            const int row = t >> 2, lane4 = t & 3;
            float* rp = sp + row*68;
            float mold = mrow[row];
            float mx = mold;
            for (int c = lane4; c < 64; c += 4) mx = fmaxf(mx, rp[c]);
            mx = fmaxf(mx, __shfl_xor_sync(0xFFFFFFFFu, mx, 1));
            mx = fmaxf(mx, __shfl_xor_sync(0xFFFFFFFFu, mx, 2));
            float a = __expf(mold - mx);
            float ssum = 0.0f;
            for (int c = lane4; c < 64; c += 4) { float p = __expf(rp[c]-mx); rp[c] = p; ssum += p; }
            ssum += __shfl_xor_sync(0xFFFFFFFFu, ssum, 1);
            ssum += __shfl_xor_sync(0xFFFFFFFFu, ssum, 2);
            if (lane4 == 0) {
                lrow[row] = lrow[row]*a + ssum;
                mrow[row] = mx;
                arow[row] = a;
            }
        }
        __syncthreads();
        {
            float al[4];
            #pragma unroll
            for (int i = 0; i < 4; i++) al[i] = arow[r0 + i];
            float acc2[4][4];
            #pragma unroll
            for (int i = 0; i < 4; i++)
                #pragma unroll
                for (int j = 0; j < 4; j++) acc2[i][j] = 0.0f;
            for (int j = 0; j < 64; j++) {
                float ra[4], rb[4];
                #pragma unroll
                for (int i = 0; i < 4; i++) ra[i] = sp[(r0+i)*68 + j];
                *(float4*)&rb[0] = *(const float4*)&sv[j*68 + c0];
                #pragma unroll
                for (int i = 0; i < 4; i++)
                    #pragma unroll
                    for (int jj = 0; jj < 4; jj++)
                        acc2[i][jj] = fmaf(ra[i], rb[jj], acc2[i][jj]);
            }
            #pragma unroll
            for (int i = 0; i < 4; i++)
                #pragma unroll
                for (int j = 0; j < 4; j++)
                    O[i][j] = O[i][j]*al[i] + acc2[i][j];
        }
    }
    #pragma unroll
    for (int i = 0; i < 4; i++) {
        float inv = 1.0f / lrow[r0 + i];
        #pragma unroll
        for (int j = 0; j < 4; j++)
            S[((size_t)b*64 + r0 + i)*Dd + h*64 + c0 + j] = O[i][j]*inv;
    }
}

// ===========================================================================
extern "C" void kernel_launch(void* const* d_in, const int* in_sizes, int n_in,
                              void* d_out, int out_size)
{
    (void)in_sizes; (void)out_size;
    const float* query = (const float*)d_in[0];
    const float* key   = (const float*)d_in[1];
    const float* value = (const float*)d_in[2];
    const int*   tidx  = (const int*)  d_in[3];
    const int*   sidx  = (const int*)  d_in[4];
    const float* tpm   = (const float*)d_in[5];
    const float* spm   = (const float*)d_in[6];
    const float* outb  = (const float*)d_in[n_in-1];
    const float* outw  = (const float*)d_in[n_in-2];
    const float* ipb   = (const float*)d_in[n_in-3];
    const float* ipw   = (const float*)d_in[n_in-4];
    const float* bv    = (const float*)d_in[n_in-5];
    const float* Wv    = (const float*)d_in[n_in-6];
    const float* bk    = (const float*)d_in[n_in-7];
    const float* Wk    = (const float*)d_in[n_in-8];
    const float* bq    = (const float*)d_in[n_in-9];
    const float* Wq    = (const float*)d_in[n_in-10];
    float* out = (float*)d_out;

    float *Q, *K, *V, *K2p, *V2p, *QS, *S, *Wcomb, *bck, *bcv, *zero;
    __half *Xq, *Xk, *Xv, *Wc;
    cudaGetSymbolAddress((void**)&Q,  g_Q);
    cudaGetSymbolAddress((void**)&K,  g_K);
    cudaGetSymbolAddress((void**)&V,  g_V);
    cudaGetSymbolAddress((void**)&K2p, g_K2);
    cudaGetSymbolAddress((void**)&V2p, g_V2);
    cudaGetSymbolAddress((void**)&QS, g_QS);
    cudaGetSymbolAddress((void**)&S,  g_S);
    cudaGetSymbolAddress((void**)&Xq, g_Xq);
    cudaGetSymbolAddress((void**)&Xk, g_Xk);
    cudaGetSymbolAddress((void**)&Xv, g_Xv);
    cudaGetSymbolAddress((void**)&Wc, g_Wc);
    cudaGetSymbolAddress((void**)&Wcomb, g_Wcomb);
    cudaGetSymbolAddress((void**)&bck, g_bck);
    cudaGetSymbolAddress((void**)&bcv, g_bcv);
    cudaGetSymbolAddress((void**)&zero, g_zero);

    cudaFuncSetAttribute(gemm_fp16,     cudaFuncAttributeMaxDynamicSharedMemorySize, GB_SMEM);
    cudaFuncSetAttribute(temporal_attn, cudaFuncAttributeMaxDynamicSharedMemorySize, TA_SMEM);
    cudaFuncSetAttribute(static_attn,   cudaFuncAttributeMaxDynamicSharedMemorySize, SA_SMEM);

    static cudaStream_t s2 = 0, s3 = 0;
    static cudaEvent_t ev0 = 0, evQx = 0, evKx = 0, evVx = 0, evQKV = 0,
                       evQS = 0, evS2 = 0, evWc = 0;
    if (!s2) {
        cudaStreamCreateWithFlags(&s2, cudaStreamNonBlocking);
        cudaStreamCreateWithFlags(&s3, cudaStreamNonBlocking);
        cudaEventCreateWithFlags(&ev0,   cudaEventDisableTiming);
        cudaEventCreateWithFlags(&evQx,  cudaEventDisableTiming);
        cudaEventCreateWithFlags(&evKx,  cudaEventDisableTiming);
        cudaEventCreateWithFlags(&evVx,  cudaEventDisableTiming);
        cudaEventCreateWithFlags(&evQKV, cudaEventDisableTiming);
        cudaEventCreateWithFlags(&evQS,  cudaEventDisableTiming);
        cudaEventCreateWithFlags(&evS2,  cudaEventDisableTiming);
        cudaEventCreateWithFlags(&evWc,  cudaEventDisableTiming);
    }

    dim3 blk(256);
    dim3 ggemm(Dd/128, Mtot/128);          // (8, 260)
    dim3 gsq(Dd/128, Dd/128);              // (8, 8)
    dim3 gsm(Dd/128, (Bb*NSs)/128);        // (8, 4)
    const int wn4 = Dd*Dd/4;
    const int xn4 = Mtot*Dd/4;
    const int wblocks = (wn4 + 255)/256;
    const int xblocks = (xn4 + 255)/256;
    __half* Wc0 = Wc;
    __half* Wc1 = Wc + (size_t)1*Dd*K2c;
    __half* Wc2 = Wc + (size_t)2*Dd*K2c;
    __half* Wc3 = Wc + (size_t)3*Dd*K2c;
    __half* Wc4 = Wc + (size_t)4*Dd*K2c;
    float* Wcombk = Wcomb;
    float* Wcombv = Wcomb + (size_t)Dd*Dd;
    const float* Wk2 = ipw + (size_t)Dd*Dd;
    const float* Wv2 = ipw + (size_t)2*Dd*Dd;

    cudaEventRecord(ev0, 0);

    // ---- fork s2: input/weight fp16 conversions ----
    cudaStreamWaitEvent(s2, ev0, 0);
    conv_hi<<<wblocks, blk, 0, s2>>>(Wq, Wc0, wn4);
    conv_hi<<<xblocks, blk, 0, s2>>>(query, Xq, xn4);
    cudaEventRecord(evQx, s2);
    conv_hi<<<wblocks, blk, 0, s2>>>(Wk, Wc1, wn4);
    conv_hi<<<xblocks, blk, 0, s2>>>(key, Xk, xn4);
    cudaEventRecord(evKx, s2);
    conv_hi<<<wblocks, blk, 0, s2>>>(Wv, Wc2, wn4);
    conv_hi<<<xblocks, blk, 0, s2>>>(value, Xv, xn4);
    cudaEventRecord(evVx, s2);

    // ---- fork s3: weight-combine chain, then QS projection ----
    cudaStreamWaitEvent(s3, ev0, 0);
    sgemm_bias<<<gsq, blk, 0, s3>>>(Wk2, Wk, zero, Wcombk, Dd, Dd, Dd, 0, sidx, 0, 1);
    sgemm_bias<<<gsq, blk, 0, s3>>>(Wv2, Wv, zero, Wcombv, Dd, Dd, Dd, 0, sidx, 0, 1);
    bias_comb<<<Dd, blk, 0, s3>>>(Wk2, bk, ipb + Dd,   bck);
    bias_comb<<<Dd, blk, 0, s3>>>(Wv2, bv, ipb + 2*Dd, bcv);
    conv_hi<<<wblocks, blk, 0, s3>>>(Wcombk, Wc3, wn4);
    conv_hi<<<wblocks, blk, 0, s3>>>(Wcombv, Wc4, wn4);
    cudaEventRecord(evWc, s3);

    // ---- main: Q/K/V GEMMs ----
    cudaStreamWaitEvent(0, evQx, 0);
    gemm_fp16<<<ggemm, blk, GB_SMEM>>>(Xq, Wc0, bq, Q, 16);
    cudaStreamWaitEvent(0, evKx, 0);
    gemm_fp16<<<ggemm, blk, GB_SMEM>>>(Xk, Wc1, bk, K, 16);
    cudaStreamWaitEvent(0, evVx, 0);
    gemm_fp16<<<ggemm, blk, GB_SMEM>>>(Xv, Wc2, bv, V, 16);
    cudaEventRecord(evQKV, 0);

    // s3: QS projection (after QKV), so temporal starts immediately on s2
    cudaStreamWaitEvent(s3, evQKV, 0);
    sgemm_bias<<<gsm, blk, 0, s3>>>(Q, ipw, ipb, QS, Bb*NSs, Dd, Dd, 1, sidx, 0, 0);
    cudaEventRecord(evQS, s3);

    // s2: temporal attention (tensor-core)
    cudaStreamWaitEvent(s2, evQKV, 0);
    temporal_attn<<<dim3(Hh, NBb, Bb), blk, TA_SMEM, s2>>>(Q, K, V, tidx, sidx, tpm, spm, out);
    cudaEventRecord(evS2, s2);

    // main: K2/V2 GEMMs, static attention, out projection
    cudaStreamWaitEvent(0, evWc, 0);
    gemm_fp16<<<ggemm, blk, GB_SMEM>>>(Xk, Wc3, bck, K2p, 16);
    gemm_fp16<<<ggemm, blk, GB_SMEM>>>(Xv, Wc4, bcv, V2p, 16);

    cudaStreamWaitEvent(0, evQS, 0);
    static_attn<<<dim3(Hh, Bb), blk, SA_SMEM>>>(QS, K2p, V2p, tidx, sidx, tpm, spm, S);
    sgemm_bias<<<gsm, blk>>>(S, outw, outb, out, Bb*NSs, Dd, Dd, 0, sidx, 1, 0);

    // join temporal branch back into main stream
    cudaStreamWaitEvent(0, evS2, 0);
}

// round 15
// speedup vs baseline: 1.4142x; 1.0987x over previous
#include <cuda_runtime.h>
#include <cuda_fp16.h>
#include <cstdint>
#include <cstddef>

// Problem constants
#define Bb   8
#define Ll   4160
#define Dd   1024
#define Hh   16
#define NBb  64
#define BLb  64
#define NSs  64
#define NTt  4096   // NB*BL
#define Mtot (Bb*Ll)      // 33280
#define K2c  2048         // row stride of fp16 operand buffers (only [0,1024) used)

// Scratch (device globals: allocation-free)
__device__ float g_Q [(size_t)Mtot*Dd];
__device__ float g_K [(size_t)Mtot*Dd];
__device__ float g_V [(size_t)Mtot*Dd];
__device__ float g_K2[(size_t)Mtot*Dd];
__device__ float g_V2[(size_t)Mtot*Dd];
__device__ float g_QS[(size_t)Bb*NSs*Dd];
__device__ float g_S [(size_t)Bb*NSs*Dd];
__device__ __half g_Xq[(size_t)Mtot*K2c];
__device__ __half g_Xk[(size_t)Mtot*K2c];
__device__ __half g_Xv[(size_t)Mtot*K2c];
__device__ __half g_Wc[5][(size_t)Dd*K2c];
__device__ float g_Wcomb[2][(size_t)Dd*Dd];
__device__ float g_bck[Dd];
__device__ float g_bcv[Dd];
__device__ float g_zero[Dd];   // zero-initialized, never written

// ===========================================================================
// helpers
// ===========================================================================
__device__ __forceinline__ uint32_t smem_u32(const void* p) {
    uint32_t a;
    asm("{ .reg .u64 t; cvta.to.shared.u64 t, %1; cvt.u32.u64 %0, t; }"
        : "=r"(a) : "l"(p));
    return a;
}
__device__ __forceinline__ void ldsm4(uint32_t* r, uint32_t addr) {
    asm volatile("ldmatrix.sync.aligned.m8n8.x4.shared.b16 {%0,%1,%2,%3}, [%4];"
                 : "=r"(r[0]), "=r"(r[1]), "=r"(r[2]), "=r"(r[3]) : "r"(addr));
}
__device__ __forceinline__ void mma16816h(float* d, const uint32_t* a,
                                          uint32_t b0, uint32_t b1) {
    asm volatile("mma.sync.aligned.m16n8k16.row.col.f32.f16.f16.f32 "
                 "{%0,%1,%2,%3}, {%4,%5,%6,%7}, {%8,%9}, {%0,%1,%2,%3};"
                 : "+f"(d[0]), "+f"(d[1]), "+f"(d[2]), "+f"(d[3])
                 : "r"(a[0]), "r"(a[1]), "r"(a[2]), "r"(a[3]), "r"(b0), "r"(b1));
}
__device__ __forceinline__ void cpasync16(uint32_t d, const void* g) {
    asm volatile("cp.async.cg.shared.global [%0], [%1], 16;" :: "r"(d), "l"(g));
}
__device__ __forceinline__ uint32_t packh2(__half a, __half b) {
    __half2 p = __halves2half2(a, b);
    return *(uint32_t*)&p;
}

// ===========================================================================
// Convert X fp32 [rows x 1024] -> Y fp16 hi-only (row stride K2c).
// ===========================================================================
__global__ void __launch_bounds__(256)
conv_hi(const float* __restrict__ X, __half* __restrict__ Y, int n4)
{
    int i = blockIdx.x * blockDim.x + threadIdx.x;
    if (i >= n4) return;
    float4 v = ((const float4*)X)[i];
    int e = i << 2;
    int row = e >> 10, col = e & 1023;
    uint2 hv = make_uint2(packh2(__float2half_rn(v.x), __float2half_rn(v.y)),
                          packh2(__float2half_rn(v.z), __float2half_rn(v.w)));
    *(uint2*)(Y + (size_t)row * K2c + col) = hv;
}

// ===========================================================================
// bias combine: out[i] = dot(W2 row i, b1) + b2[i].  grid = 1024 blocks.
// ===========================================================================
__global__ void __launch_bounds__(256)
bias_comb(const float* __restrict__ W2, const float* __restrict__ b1,
          const float* __restrict__ b2, float* __restrict__ out)
{
    __shared__ float red[256];
    int i = blockIdx.x;
    float s = 0.0f;
    for (int k = threadIdx.x; k < Dd; k += 256)
        s += W2[(size_t)i * Dd + k] * b1[k];
    red[threadIdx.x] = s;
    __syncthreads();
    for (int st = 128; st > 0; st >>= 1) {
        if (threadIdx.x < st) red[threadIdx.x] += red[threadIdx.x + st];
        __syncthreads();
    }
    if (threadIdx.x == 0) out[i] = red[0] + b2[i];
}

// ===========================================================================
// fp16 TN GEMM (2 CTA/SM): C[M,1024] = A'[M,:64*kchunks] @ W'[1024,...]^T
// ===========================================================================
#define GB_SMEM (2*32768)

__global__ void __launch_bounds__(256)
gemm_fp16(const __half* __restrict__ A, const __half* __restrict__ W,
          const float* __restrict__ bias, float* __restrict__ C, int kchunks)
{
    extern __shared__ char gsm[];
    const uint32_t sb = smem_u32(gsm);
    const int t = threadIdx.x;
    const int m0 = blockIdx.y * 128;
    const int n0 = blockIdx.x * 128;

    const int l = t & 31, wid = t >> 5;
    const int wm = (wid & 3) * 32;
    const int wn = (wid >> 2) * 64;
    const int lr = (l & 7) + ((l >> 3) & 1) * 8;
    const int khalf = l >> 4;

    uint32_t aoff[2], asw[2];
    #pragma unroll
    for (int i = 0; i < 2; i++) {
        int row = wm + i * 16 + lr;
        aoff[i] = row * 128;
        asw[i]  = row & 7;
    }
    uint32_t boff[4], bsw[4];
    #pragma unroll
    for (int pr = 0; pr < 4; pr++) {
        int row = wn + pr * 16 + lr;
        boff[pr] = row * 128;
        bsw[pr]  = row & 7;
    }

    float acc[2][8][4];
    #pragma unroll
    for (int i = 0; i < 2; i++)
        #pragma unroll
        for (int j = 0; j < 8; j++)
            #pragma unroll
            for (int z = 0; z < 4; z++) acc[i][j][z] = 0.0f;

    const int NCH = kchunks;

    auto load_chunk = [&](int s) {
        int p = s & 1;
        uint32_t sa  = sb + p * 32768;
        uint32_t sbb = sa + 16384;
        const __half* Ag = A + (size_t)m0 * K2c + s * 64;
        const __half* Wg = W + (size_t)n0 * K2c + s * 64;
        #pragma unroll
        for (int it = 0; it < 4; it++) {
            int e = it * 256 + t;
            int row = e >> 3, seg = e & 7;
            uint32_t sw = (uint32_t)((seg ^ (row & 7)) << 4);
            cpasync16(sa  + row * 128 + sw, Ag + (size_t)row * K2c + seg * 8);
            cpasync16(sbb + row * 128 + sw, Wg + (size_t)row * K2c + seg * 8);
        }
        asm volatile("cp.async.commit_group;");
    };

    load_chunk(0);

    for (int s = 0; s < NCH; s++) {
        if (s + 1 < NCH) {
            load_chunk(s + 1);
            asm volatile("cp.async.wait_group 1;");
        } else {
            asm volatile("cp.async.wait_group 0;");
        }
        __syncthreads();

        int p = s & 1;
        uint32_t sa  = sb + p * 32768;
        uint32_t sbb = sa + 16384;
        #pragma unroll
        for (int k2 = 0; k2 < 4; k2++) {
            uint32_t areg[2][4];
            #pragma unroll
            for (int i = 0; i < 2; i++)
                ldsm4(areg[i], sa + aoff[i] + ((((uint32_t)(k2*2 + khalf)) ^ asw[i]) << 4));
            uint32_t breg[4][4];
            #pragma unroll
            for (int pr = 0; pr < 4; pr++)
                ldsm4(breg[pr], sbb + boff[pr] + ((((uint32_t)(k2*2 + khalf)) ^ bsw[pr]) << 4));
            #pragma unroll
            for (int i = 0; i < 2; i++)
                #pragma unroll
                for (int j = 0; j < 8; j++)
                    mma16816h(acc[i][j], areg[i],
                              breg[j >> 1][j & 1], breg[j >> 1][2 + (j & 1)]);
        }
        __syncthreads();
    }

    const int r = l >> 2, q = l & 3;
    #pragma unroll
    for (int i = 0; i < 2; i++) {
        int row = m0 + wm + i * 16 + r;
        #pragma unroll
        for (int j = 0; j < 8; j++) {
            int col = n0 + wn + j * 8 + q * 2;
            float b0 = bias[col], b1 = bias[col + 1];
            *(float2*)(C + (size_t)row * 1024 + col) =
                make_float2(acc[i][j][0] + b0, acc[i][j][1] + b1);
            *(float2*)(C + (size_t)(row + 8) * 1024 + col) =
                make_float2(acc[i][j][2] + b0, acc[i][j][3] + b1);
        }
    }
}

// ===========================================================================
// SIMT SGEMM, 128x128 tiles: C = A @ op(W) + bias
// modeW: 0 -> W [N,K] row-major (A@W^T);  1 -> W [K,N] row-major (A@W)
// modeA: 1 = gather rows via sidx; modeC: 1 = scatter rows to b*L+NT+q
// ===========================================================================
__global__ void __launch_bounds__(256)
sgemm_bias(const float* __restrict__ A, const float* __restrict__ W,
           const float* __restrict__ bias, float* __restrict__ C,
           int M, int N, int K,
           int modeA, const int* __restrict__ sidx, int modeC, int modeW)
{
    __shared__ float As[8][128];
    __shared__ float Bs[8][128];
    const int t    = threadIdx.x;
    const int row0 = blockIdx.y * 128;
    const int col0 = blockIdx.x * 128;
    const int a_r = t >> 1;
    const int a_c = (t & 1) << 2;
    int arow = row0 + a_r;
    size_t a_base;
    if (modeA == 1) {
        int bi = arow >> 6, qq = arow & 63;
        a_base = ((size_t)bi * Ll + (size_t)sidx[qq]) * (size_t)K;
    } else {
        a_base = (size_t)arow * (size_t)K;
    }
    const size_t w_base = (size_t)(col0 + a_r) * (size_t)K;
    const int kk2 = t >> 5;
    const int n4  = (t & 31) << 2;
    const int tr = (t >> 4) << 3;
    const int tc = (t & 15) << 3;
    float acc[8][8];
    #pragma unroll
    for (int i = 0; i < 8; i++)
        #pragma unroll
        for (int j = 0; j < 8; j++) acc[i][j] = 0.0f;
    for (int k0 = 0; k0 < K; k0 += 8) {
        float4 av = *(const float4*)(A + a_base + k0 + a_c);
        As[a_c+0][a_r] = av.x; As[a_c+1][a_r] = av.y;
        As[a_c+2][a_r] = av.z; As[a_c+3][a_r] = av.w;
        if (modeW == 0) {
            float4 wv = *(const float4*)(W + w_base + k0 + a_c);
            Bs[a_c+0][a_r] = wv.x; Bs[a_c+1][a_r] = wv.y;
            Bs[a_c+2][a_r] = wv.z; Bs[a_c+3][a_r] = wv.w;
        } else {
            float4 wv = *(const float4*)(W + (size_t)(k0 + kk2) * N + col0 + n4);
            *(float4*)&Bs[kk2][n4] = wv;
        }
        __syncthreads();
        #pragma unroll
        for (int k = 0; k < 8; k++) {
            float ra[8], rb[8];
            *(float4*)&ra[0] = *(const float4*)&As[k][tr];
            *(float4*)&ra[4] = *(const float4*)&As[k][tr+4];
            *(float4*)&rb[0] = *(const float4*)&Bs[k][tc];
            *(float4*)&rb[4] = *(const float4*)&Bs[k][tc+4];
            #pragma unroll
            for (int i = 0; i < 8; i++)
                #pragma unroll
                for (int j = 0; j < 8; j++)
                    acc[i][j] = fmaf(ra[i], rb[j], acc[i][j]);
        }
        __syncthreads();
    }
    #pragma unroll
    for (int i = 0; i < 8; i++) {
        int r = row0 + tr + i;
        int orow = (modeC == 1) ? ((r >> 6) * Ll + NTt + (r & 63)) : r;
        float* cp = C + (size_t)orow * (size_t)N + col0 + tc;
        #pragma unroll
        for (int j = 0; j < 8; j++)
            cp[j] = acc[i][j] + bias[col0 + tc + j];
    }
}

// ===========================================================================
// Temporal block attention — tensor-core version (R14, unchanged).
// ===========================================================================
#define TA_SMEM (62464 + 33792 + 512)

__global__ void __launch_bounds__(256)
temporal_attn(const float* __restrict__ Q, const float* __restrict__ K,
              const float* __restrict__ V,
              const int* __restrict__ tidx, const int* __restrict__ sidx,
              const float* __restrict__ tpm, const float* __restrict__ spm,
              float* __restrict__ out)
{
    const int h = blockIdx.x, nb = blockIdx.y, b = blockIdx.z;
    const int t = threadIdx.x;
    extern __shared__ char smc[];
    __half* sqh  = (__half*)smc;        // 64 x 72
    __half* skh  = sqh + 4608;          // 128 x 72
    __half* svT  = skh + 9216;          // 64 x 136
    __half* sp16 = svT + 8704;          // 64 x 136
    float*  sp   = (float*)(smc + 62464);
    float*  sbias= sp + 64*132;

    const uint32_t sqh_u  = smem_u32(sqh);
    const uint32_t skh_u  = smem_u32(skh);
    const uint32_t svT_u  = smem_u32(svT);
    const uint32_t sp16_u = smem_u32(sp16);

    if (t < 128) {
        float mk = (t < 64) ? tpm[((b*NBb)+nb)*BLb + t] : spm[b*NSs + (t-64)];
        sbias[t] = (mk == 1.0f) ? 0.0f : -1e30f;
    }
    for (int e = t; e < 64*64; e += 256) {
        int r = e >> 6, k = e & 63;
        int grow = tidx[nb*64 + r];
        sqh[r*72 + k] = __float2half_rn(Q[((size_t)b*Ll + grow)*Dd + h*64 + k]);
    }
    for (int e = t; e < 128*64; e += 256) {
        int r = e >> 6, k = e & 63;
        int grow = (r < 64) ? tidx[nb*64 + r] : sidx[r - 64];
        skh[r*72 + k] = __float2half_rn(K[((size_t)b*Ll + grow)*Dd + h*64 + k]);
    }
    for (int e = t; e < 128*64; e += 256) {
        int j = e >> 6, d = e & 63;
        int grow = (j < 64) ? tidx[nb*64 + j] : sidx[j - 64];
        svT[d*136 + j] = __float2half_rn(V[((size_t)b*Ll + grow)*Dd + h*64 + d]);
    }
    __syncthreads();

    const int l = t & 31, wid = t >> 5;
    const int lr = (l & 7) + ((l >> 3) & 1) * 8;
    const int khalf = l >> 4;
    const int rr = l >> 2, qq = l & 3;

    // logits = Q @ K^T * scale + bias
    {
        const int wm = (wid & 1) * 32;
        const int wn = (wid >> 1) * 32;
        float acc[2][4][4];
        #pragma unroll
        for (int i = 0; i < 2; i++)
            #pragma unroll
            for (int j = 0; j < 4; j++)
                #pragma unroll
                for (int z = 0; z < 4; z++) acc[i][j][z] = 0.0f;
        #pragma unroll
        for (int k2 = 0; k2 < 4; k2++) {
            const uint32_t kc = (uint32_t)(k2*2 + khalf);
            uint32_t areg[2][4], breg[2][4];
            #pragma unroll
            for (int i = 0; i < 2; i++)
                ldsm4(areg[i], sqh_u + (uint32_t)(wm + i*16 + lr)*144u + kc*16u);
            #pragma unroll
            for (int pr = 0; pr < 2; pr++)
                ldsm4(breg[pr], skh_u + (uint32_t)(wn + pr*16 + lr)*144u + kc*16u);
            #pragma unroll
            for (int i = 0; i < 2; i++)
                #pragma unroll
                for (int j = 0; j < 4; j++)
                    mma16816h(acc[i][j], areg[i],
                              breg[j >> 1][j & 1], breg[j >> 1][2 + (j & 1)]);
        }
        #pragma unroll
        for (int i = 0; i < 2; i++) {
            int row = wm + i*16 + rr;
            #pragma unroll
            for (int j = 0; j < 4; j++) {
                int col = wn + j*8 + qq*2;
                float b0 = sbias[col], b1 = sbias[col+1];
                sp[row*132 + col]       = acc[i][j][0]*0.125f + b0;
                sp[row*132 + col + 1]   = acc[i][j][1]*0.125f + b1;
                sp[(row+8)*132 + col]   = acc[i][j][2]*0.125f + b0;
                sp[(row+8)*132 + col+1] = acc[i][j][3]*0.125f + b1;
            }
        }
    }
    __syncthreads();

    // softmax -> fp16
    {
        const int row = t >> 2, lane4 = t & 3;
        float* rp = sp + row*132;
        __half* rp16 = sp16 + row*136;
        float mx = -1e30f;
        for (int c = lane4; c < 128; c += 4) mx = fmaxf(mx, rp[c]);
        mx = fmaxf(mx, __shfl_xor_sync(0xFFFFFFFFu, mx, 1));
        mx = fmaxf(mx, __shfl_xor_sync(0xFFFFFFFFu, mx, 2));
        float s = 0.0f;
        for (int c = lane4; c < 128; c += 4) { float p = __expf(rp[c]-mx); rp[c] = p; s += p; }
        s += __shfl_xor_sync(0xFFFFFFFFu, s, 1);
        s += __shfl_xor_sync(0xFFFFFFFFu, s, 2);
        float inv = 1.0f / s;
        for (int c = lane4; c < 128; c += 4) rp16[c] = __float2half_rn(rp[c]*inv);
    }
    __syncthreads();

    // out = P @ V
    {
        const int wm = (wid & 1) * 32;
        const int wn = (wid >> 1) * 16;
        float acc[2][2][4];
        #pragma unroll
        for (int i = 0; i < 2; i++)
            #pragma unroll
            for (int j = 0; j < 2; j++)
                #pragma unroll
                for (int z = 0; z < 4; z++) acc[i][j][z] = 0.0f;
        #pragma unroll
        for (int k2 = 0; k2 < 8; k2++) {
            const uint32_t kc = (uint32_t)(k2*2 + khalf);
            uint32_t areg[2][4], breg[4];
            #pragma unroll
            for (int i = 0; i < 2; i++)
                ldsm4(areg[i], sp16_u + (uint32_t)(wm + i*16 + lr)*272u + kc*16u);
            ldsm4(breg, svT_u + (uint32_t)(wn + lr)*272u + kc*16u);
            #pragma unroll
            for (int i = 0; i < 2; i++)
                #pragma unroll
                for (int j = 0; j < 2; j++)
                    mma16816h(acc[i][j], areg[i], breg[j], breg[2 + j]);
        }
        #pragma unroll
        for (int i = 0; i < 2; i++) {
            int row = wm + i*16 + rr;
            #pragma unroll
            for (int j = 0; j < 2; j++) {
                int col = h*64 + wn + j*8 + qq*2;
                *(float2*)(out + ((size_t)b*Ll + nb*64 + row)*Dd + col) =
                    make_float2(acc[i][j][0], acc[i][j][1]);
                *(float2*)(out + ((size_t)b*Ll + nb*64 + row + 8)*Dd + col) =
                    make_float2(acc[i][j][2], acc[i][j][3]);
            }
        }
    }
}

// ===========================================================================
// Static attention — tensor-core flash version.
// Per chunk of 64 KV: QK (64x64x64) + PV (64x64x64) via mma.sync fp16.
// SMEM: sqh/skh/svT/sp16 64x72 halves (9216 B each), sp 64x68 fp32 (17408 B),
//       mrow/lrow/arow/sb2 64 floats each.
// ===========================================================================
#define SA_SMEM 55296

__global__ void __launch_bounds__(256)
static_attn(const float* __restrict__ Qs, const float* __restrict__ K2,
            const float* __restrict__ V2,
            const int* __restrict__ tidx, const int* __restrict__ sidx,
            const float* __restrict__ tpm, const float* __restrict__ spm,
            float* __restrict__ S)
{
    const int h = blockIdx.x, b = blockIdx.y;
    const int t = threadIdx.x;
    extern __shared__ char smc[];
    __half* sqh  = (__half*)smc;            // 64 x 72
    __half* skh  = sqh + 4608;              // 64 x 72
    __half* svT  = skh + 4608;              // 64 x 72 (rows=d, cols=j)
    __half* sp16 = svT + 4608;              // 64 x 72
    float*  sp   = (float*)(smc + 36864);   // 64 x 68
    float*  mrow = (float*)(smc + 54272);
    float*  lrow = mrow + 64;
    float*  arow = lrow + 64;
    float*  sb2  = arow + 64;

    const uint32_t sqh_u  = smem_u32(sqh);
    const uint32_t skh_u  = smem_u32(skh);
    const uint32_t svT_u  = smem_u32(svT);
    const uint32_t sp16_u = smem_u32(sp16);

    for (int e = t; e < 4096; e += 256) {
        int r = e >> 6, k = e & 63;
        sqh[r*72 + k] = __float2half_rn(Qs[((size_t)b*64 + r)*Dd + h*64 + k]);
    }
    if (t < 64) { mrow[t] = -1e30f; lrow[t] = 0.0f; }

    const int l = t & 31, wid = t >> 5;
    const int lr = (l & 7) + ((l >> 3) & 1) * 8;
    const int khalf = l >> 4;
    const int rr = l >> 2, qq = l & 3;
    const int wm = (wid & 1) * 32;   // 2 warps over rows
    const int wn = (wid >> 1) * 16;  // 4 warps over cols

    float O[2][2][4];
    #pragma unroll
    for (int i = 0; i < 2; i++)
        #pragma unroll
        for (int j = 0; j < 2; j++)
            #pragma unroll
            for (int z = 0; z < 4; z++) O[i][j][z] = 0.0f;

    for (int jc = 0; jc < 65; jc++) {
        int base = jc * 64;
        __syncthreads();
        for (int e = t; e < 4096; e += 256) {
            int j = e >> 6, k = e & 63;
            int jj = base + j;
            int grow = (jj < NTt) ? tidx[jj] : sidx[jj - NTt];
            size_t gb = ((size_t)b*Ll + grow)*Dd + h*64 + k;
            skh[j*72 + k] = __float2half_rn(K2[gb]);
            svT[k*72 + j] = __float2half_rn(V2[gb]);
        }
        if (t < 64) {
            int jj = base + t;
            float mk = (jj < NTt) ? tpm[b*NTt + jj] : spm[b*NSs + (jj - NTt)];
            sb2[t] = (mk == 1.0f) ? 0.0f : -1e30f;
        }
        __syncthreads();

        // ---- logits chunk: Q @ Kc^T ----
        {
            float acc[2][2][4];
            #pragma unroll
            for (int i = 0; i < 2; i++)
                #pragma unroll
                for (int j = 0; j < 2; j++)
                    #pragma unroll
                    for (int z = 0; z < 4; z++) acc[i][j][z] = 0.0f;
            #pragma unroll
            for (int k2 = 0; k2 < 4; k2++) {
                const uint32_t kc = (uint32_t)(k2*2 + khalf);
                uint32_t areg[2][4], breg[4];
                #pragma unroll
                for (int i = 0; i < 2; i++)
                    ldsm4(areg[i], sqh_u + (uint32_t)(wm + i*16 + lr)*144u + kc*16u);
                ldsm4(breg, skh_u + (uint32_t)(wn + lr)*144u + kc*16u);
                #pragma unroll
                for (int i = 0; i < 2; i++)
                    #pragma unroll
                    for (int j = 0; j < 2; j++)
                        mma16816h(acc[i][j], areg[i], breg[j], breg[2 + j]);
            }
            #pragma unroll
            for (int i = 0; i < 2; i++) {
                int row = wm + i*16 + rr;
                #pragma unroll
                for (int j = 0; j < 2; j++) {
                    int col = wn + j*8 + qq*2;
                    float b0 = sb2[col], b1 = sb2[col+1];
                    sp[row*68 + col]       = acc[i][j][0]*0.125f + b0;
                    sp[row*68 + col + 1]   = acc[i][j][1]*0.125f + b1;
                    sp[(row+8)*68 + col]   = acc[i][j][2]*0.125f + b0;
                    sp[(row+8)*68 + col+1] = acc[i][j][3]*0.125f + b1;
                }
            }
        }
        __syncthreads();

        // ---- running softmax update (4 threads/row), emit fp16 p ----
        {
            const int row = t >> 2, lane4 = t & 3;
            float* rp = sp + row*68;
            __half* rp16 = sp16 + row*72;
            float mold = mrow[row];
            float mx = mold;
            for (int c = lane4; c < 64; c += 4) mx = fmaxf(mx, rp[c]);
            mx = fmaxf(mx, __shfl_xor_sync(0xFFFFFFFFu, mx, 1));
            mx = fmaxf(mx, __shfl_xor_sync(0xFFFFFFFFu, mx, 2));
            float a = __expf(mold - mx);
            float ssum = 0.0f;
            for (int c = lane4; c < 64; c += 4) {
                float p = __expf(rp[c]-mx);
                rp16[c] = __float2half_rn(p);
                ssum += p;
            }
            ssum += __shfl_xor_sync(0xFFFFFFFFu, ssum, 1);
            ssum += __shfl_xor_sync(0xFFFFFFFFu, ssum, 2);
            if (lane4 == 0) {
                lrow[row] = lrow[row]*a + ssum;
                mrow[row] = mx;
                arow[row] = a;
            }
        }
        __syncthreads();

        // ---- rescale O and accumulate P @ Vc ----
        {
            #pragma unroll
            for (int i = 0; i < 2; i++) {
                float a0 = arow[wm + i*16 + rr];
                float a1 = arow[wm + i*16 + rr + 8];
                #pragma unroll
                for (int j = 0; j < 2; j++) {
                    O[i][j][0] *= a0; O[i][j][1] *= a0;
                    O[i][j][2] *= a1; O[i][j][3] *= a1;
                }
            }
            #pragma unroll
            for (int k2 = 0; k2 < 4; k2++) {
                const uint32_t kc = (uint32_t)(k2*2 + khalf);
                uint32_t areg[2][4], breg[4];
                #pragma unroll
                for (int i = 0; i < 2; i++)
                    ldsm4(areg[i], sp16_u + (uint32_t)(wm + i*16 + lr)*144u + kc*16u);
                ldsm4(breg, svT_u + (uint32_t)(wn + lr)*144u + kc*16u);
                #pragma unroll
                for (int i = 0; i < 2; i++)
                    #pragma unroll
                    for (int j = 0; j < 2; j++)
                        mma16816h(O[i][j], areg[i], breg[j], breg[2 + j]);
            }
        }
    }

    #pragma unroll
    for (int i = 0; i < 2; i++) {
        int row = wm + i*16 + rr;
        float inv0 = 1.0f / lrow[row];
        float inv1 = 1.0f / lrow[row + 8];
        #pragma unroll
        for (int j = 0; j < 2; j++) {
            int col = h*64 + wn + j*8 + qq*2;
            *(float2*)(S + ((size_t)b*64 + row)*Dd + col) =
                make_float2(O[i][j][0]*inv0, O[i][j][1]*inv0);
            *(float2*)(S + ((size_t)b*64 + row + 8)*Dd + col) =
                make_float2(O[i][j][2]*inv1, O[i][j][3]*inv1);
        }
    }
}

// ===========================================================================
extern "C" void kernel_launch(void* const* d_in, const int* in_sizes, int n_in,
                              void* d_out, int out_size)
{
    (void)in_sizes; (void)out_size;
    const float* query = (const float*)d_in[0];
    const float* key   = (const float*)d_in[1];
    const float* value = (const float*)d_in[2];
    const int*   tidx  = (const int*)  d_in[3];
    const int*   sidx  = (const int*)  d_in[4];
    const float* tpm   = (const float*)d_in[5];
    const float* spm   = (const float*)d_in[6];
    const float* outb  = (const float*)d_in[n_in-1];
    const float* outw  = (const float*)d_in[n_in-2];
    const float* ipb   = (const float*)d_in[n_in-3];
    const float* ipw   = (const float*)d_in[n_in-4];
    const float* bv    = (const float*)d_in[n_in-5];
    const float* Wv    = (const float*)d_in[n_in-6];
    const float* bk    = (const float*)d_in[n_in-7];
    const float* Wk    = (const float*)d_in[n_in-8];
    const float* bq    = (const float*)d_in[n_in-9];
    const float* Wq    = (const float*)d_in[n_in-10];
    float* out = (float*)d_out;

    float *Q, *K, *V, *K2p, *V2p, *QS, *S, *Wcomb, *bck, *bcv, *zero;
    __half *Xq, *Xk, *Xv, *Wc;
    cudaGetSymbolAddress((void**)&Q,  g_Q);
    cudaGetSymbolAddress((void**)&K,  g_K);
    cudaGetSymbolAddress((void**)&V,  g_V);
    cudaGetSymbolAddress((void**)&K2p, g_K2);
    cudaGetSymbolAddress((void**)&V2p, g_V2);
    cudaGetSymbolAddress((void**)&QS, g_QS);
    cudaGetSymbolAddress((void**)&S,  g_S);
    cudaGetSymbolAddress((void**)&Xq, g_Xq);
    cudaGetSymbolAddress((void**)&Xk, g_Xk);
    cudaGetSymbolAddress((void**)&Xv, g_Xv);
    cudaGetSymbolAddress((void**)&Wc, g_Wc);
    cudaGetSymbolAddress((void**)&Wcomb, g_Wcomb);
    cudaGetSymbolAddress((void**)&bck, g_bck);
    cudaGetSymbolAddress((void**)&bcv, g_bcv);
    cudaGetSymbolAddress((void**)&zero, g_zero);

    cudaFuncSetAttribute(gemm_fp16,     cudaFuncAttributeMaxDynamicSharedMemorySize, GB_SMEM);
    cudaFuncSetAttribute(temporal_attn, cudaFuncAttributeMaxDynamicSharedMemorySize, TA_SMEM);
    cudaFuncSetAttribute(static_attn,   cudaFuncAttributeMaxDynamicSharedMemorySize, SA_SMEM);

    static cudaStream_t s2 = 0, s3 = 0;
    static cudaEvent_t ev0 = 0, evQx = 0, evKx = 0, evVx = 0, evQKV = 0,
                       evQS = 0, evS2 = 0, evWc = 0;
    if (!s2) {
        cudaStreamCreateWithFlags(&s2, cudaStreamNonBlocking);
        cudaStreamCreateWithFlags(&s3, cudaStreamNonBlocking);
        cudaEventCreateWithFlags(&ev0,   cudaEventDisableTiming);
        cudaEventCreateWithFlags(&evQx,  cudaEventDisableTiming);
        cudaEventCreateWithFlags(&evKx,  cudaEventDisableTiming);
        cudaEventCreateWithFlags(&evVx,  cudaEventDisableTiming);
        cudaEventCreateWithFlags(&evQKV, cudaEventDisableTiming);
        cudaEventCreateWithFlags(&evQS,  cudaEventDisableTiming);
        cudaEventCreateWithFlags(&evS2,  cudaEventDisableTiming);
        cudaEventCreateWithFlags(&evWc,  cudaEventDisableTiming);
    }

    dim3 blk(256);
    dim3 ggemm(Dd/128, Mtot/128);          // (8, 260)
    dim3 gsq(Dd/128, Dd/128);              // (8, 8)
    dim3 gsm(Dd/128, (Bb*NSs)/128);        // (8, 4)
    const int wn4 = Dd*Dd/4;
    const int xn4 = Mtot*Dd/4;
    const int wblocks = (wn4 + 255)/256;
    const int xblocks = (xn4 + 255)/256;
    __half* Wc0 = Wc;
    __half* Wc1 = Wc + (size_t)1*Dd*K2c;
    __half* Wc2 = Wc + (size_t)2*Dd*K2c;
    __half* Wc3 = Wc + (size_t)3*Dd*K2c;
    __half* Wc4 = Wc + (size_t)4*Dd*K2c;
    float* Wcombk = Wcomb;
    float* Wcombv = Wcomb + (size_t)Dd*Dd;
    const float* Wk2 = ipw + (size_t)Dd*Dd;
    const float* Wv2 = ipw + (size_t)2*Dd*Dd;

    cudaEventRecord(ev0, 0);

    // ---- fork s2: input/weight fp16 conversions ----
    cudaStreamWaitEvent(s2, ev0, 0);
    conv_hi<<<wblocks, blk, 0, s2>>>(Wq, Wc0, wn4);
    conv_hi<<<xblocks, blk, 0, s2>>>(query, Xq, xn4);
    cudaEventRecord(evQx, s2);
    conv_hi<<<wblocks, blk, 0, s2>>>(Wk, Wc1, wn4);
    conv_hi<<<xblocks, blk, 0, s2>>>(key, Xk, xn4);
    cudaEventRecord(evKx, s2);
    conv_hi<<<wblocks, blk, 0, s2>>>(Wv, Wc2, wn4);
    conv_hi<<<xblocks, blk, 0, s2>>>(value, Xv, xn4);
    cudaEventRecord(evVx, s2);

    // ---- fork s3: weight-combine chain, then QS projection ----
    cudaStreamWaitEvent(s3, ev0, 0);
    sgemm_bias<<<gsq, blk, 0, s3>>>(Wk2, Wk, zero, Wcombk, Dd, Dd, Dd, 0, sidx, 0, 1);
    sgemm_bias<<<gsq, blk, 0, s3>>>(Wv2, Wv, zero, Wcombv, Dd, Dd, Dd, 0, sidx, 0, 1);
    bias_comb<<<Dd, blk, 0, s3>>>(Wk2, bk, ipb + Dd,   bck);
    bias_comb<<<Dd, blk, 0, s3>>>(Wv2, bv, ipb + 2*Dd, bcv);
    conv_hi<<<wblocks, blk, 0, s3>>>(Wcombk, Wc3, wn4);
    conv_hi<<<wblocks, blk, 0, s3>>>(Wcombv, Wc4, wn4);
    cudaEventRecord(evWc, s3);

    // ---- main: Q/K/V GEMMs ----
    cudaStreamWaitEvent(0, evQx, 0);
    gemm_fp16<<<ggemm, blk, GB_SMEM>>>(Xq, Wc0, bq, Q, 16);
    cudaStreamWaitEvent(0, evKx, 0);
    gemm_fp16<<<ggemm, blk, GB_SMEM>>>(Xk, Wc1, bk, K, 16);
    cudaStreamWaitEvent(0, evVx, 0);
    gemm_fp16<<<ggemm, blk, GB_SMEM>>>(Xv, Wc2, bv, V, 16);
    cudaEventRecord(evQKV, 0);

    // s3: QS projection (after QKV)
    cudaStreamWaitEvent(s3, evQKV, 0);
    sgemm_bias<<<gsm, blk, 0, s3>>>(Q, ipw, ipb, QS, Bb*NSs, Dd, Dd, 1, sidx, 0, 0);
    cudaEventRecord(evQS, s3);

    // s2: temporal attention (tensor-core)
    cudaStreamWaitEvent(s2, evQKV, 0);
    temporal_attn<<<dim3(Hh, NBb, Bb), blk, TA_SMEM, s2>>>(Q, K, V, tidx, sidx, tpm, spm, out);
    cudaEventRecord(evS2, s2);

    // main: K2/V2 GEMMs, static attention (tensor-core), out projection
    cudaStreamWaitEvent(0, evWc, 0);
    gemm_fp16<<<ggemm, blk, GB_SMEM>>>(Xk, Wc3, bck, K2p, 16);
    gemm_fp16<<<ggemm, blk, GB_SMEM>>>(Xv, Wc4, bcv, V2p, 16);

    cudaStreamWaitEvent(0, evQS, 0);
    static_attn<<<dim3(Hh, Bb), blk, SA_SMEM>>>(QS, K2p, V2p, tidx, sidx, tpm, spm, S);
    sgemm_bias<<<gsm, blk>>>(S, outw, outb, out, Bb*NSs, Dd, Dd, 0, sidx, 1, 0);

    // join temporal branch back into main stream
    cudaStreamWaitEvent(0, evS2, 0);
}